// round 10
// baseline (speedup 1.0000x reference)
#include <cuda_runtime.h>
#include <cuda_bf16.h>
#include <math.h>
#include <stdint.h>
#include <mma.h>

using namespace nvcuda;

#define NN 100000
#define NP 100096
#define EE 600000
#define DD 128
#define SS 3
#define GG 64
#define OUTD 2
#define NPS (SS * NP)
#define M_TILES (NP / 128)        // 782

// ---------------- device scratch ----------------
__device__ __nv_bfloat16 g_xb[NP * DD];           // bf16 x
__device__ __nv_bfloat16 g_hb3[SS * NP * DD];     // per-edge-set hidden, bf16
__device__ __nv_bfloat16 g_agg3[SS * NP * DD];    // gathered means
__device__ __nv_bfloat16 g_gi3[SS * NP * 3 * DD];
__device__ __nv_bfloat16 g_gh3[SS * NP * 3 * DD];
__device__ __nv_bfloat16 g_wcb[SS * 2 * 3 * DD * DD];
__device__ __nv_bfloat16 g_wihb[SS * 3 * DD * DD];
__device__ __nv_bfloat16 g_whhb[SS * 3 * DD * DD];
__device__ __nv_bfloat16 g_Wb[SS * 2 * DD * DD];
__device__ float g_pool[GG * DD];
__device__ float g_cnt[GG];
__device__ int   g_bsrc[EE];
__device__ int   g_ecnt[NPS];
__device__ int   g_ecur[NPS];
__device__ int   g_eoff[NPS + 1];

// ---------------- tiny utils ----------------
__global__ void zero_kernel(float* __restrict__ p, int n4) {
    int i = blockIdx.x * blockDim.x + threadIdx.x;
    if (i < n4) ((float4*)p)[i] = make_float4(0.f, 0.f, 0.f, 0.f);
}
__global__ void copy_pad_kernel(const float* __restrict__ x, __nv_bfloat16* __restrict__ xb) {
    int i = blockIdx.x * blockDim.x + threadIdx.x;
    if (i >= NP * 32) return;
    int n = i >> 5;
    float4 v = make_float4(0.f, 0.f, 0.f, 0.f);
    if (n < NN) v = ((const float4*)x)[i];
    *(__nv_bfloat162*)(xb + (size_t)i * 4)     = __floats2bfloat162_rn(v.x, v.y);
    *(__nv_bfloat162*)(xb + (size_t)i * 4 + 2) = __floats2bfloat162_rn(v.z, v.w);
}
__global__ void cvt_bf16_kernel(const float* __restrict__ src,
                                __nv_bfloat16* __restrict__ dst, int n4) {
    int i = blockIdx.x * blockDim.x + threadIdx.x;
    if (i >= n4) return;
    float4 v = ((const float4*)src)[i];
    *(__nv_bfloat162*)(dst + (size_t)i * 4)     = __floats2bfloat162_rn(v.x, v.y);
    *(__nv_bfloat162*)(dst + (size_t)i * 4 + 2) = __floats2bfloat162_rn(v.z, v.w);
}
__global__ void zero2_ints(int* __restrict__ a, int* __restrict__ b, int n) {
    int i = blockIdx.x * blockDim.x + threadIdx.x;
    if (i < n) { a[i] = 0; b[i] = 0; }
}

// ---------------- CSR build ----------------
__global__ void ecount_kernel(const int* __restrict__ dst, const int* __restrict__ attr,
                              int* __restrict__ cnt, int E) {
    int e = blockIdx.x * blockDim.x + threadIdx.x;
    if (e < E) atomicAdd(&cnt[attr[e] * NP + dst[e]], 1);
}
__global__ void scan_kernel(const int* __restrict__ cnt, int* __restrict__ off, int n) {
    __shared__ int ssum[1024];
    int t = threadIdx.x;
    int per = (n + 1023) / 1024;
    int b0 = t * per;
    int b1 = b0 + per; if (b1 > n) b1 = n; if (b0 > n) b0 = n;
    int s = 0;
    for (int i = b0; i < b1; i++) s += cnt[i];
    ssum[t] = s;
    __syncthreads();
    for (int d = 1; d < 1024; d <<= 1) {
        int v = (t >= d) ? ssum[t - d] : 0;
        __syncthreads();
        ssum[t] += v;
        __syncthreads();
    }
    int run = (t == 0) ? 0 : ssum[t - 1];
    if (t == 1023) off[n] = ssum[1023];
    for (int i = b0; i < b1; i++) { off[i] = run; run += cnt[i]; }
}
__global__ void fill_kernel(const int* __restrict__ src, const int* __restrict__ dst,
                            const int* __restrict__ attr, const int* __restrict__ off,
                            int* __restrict__ cur, int* __restrict__ bsrc, int E) {
    int e = blockIdx.x * blockDim.x + threadIdx.x;
    if (e >= E) return;
    int idx = attr[e] * NP + dst[e];
    int pos = off[idx] + atomicAdd(&cur[idx], 1);
    bsrc[pos] = src[e];
}

// ---------------- gather all 3 types ----------------
struct Feat3 { const __nv_bfloat16* p[3]; };

__global__ void gather3_kernel(const int* __restrict__ off, const int* __restrict__ bsrc,
                               Feat3 f, __nv_bfloat16* __restrict__ agg3) {
    int w = (blockIdx.x * blockDim.x + threadIdx.x) >> 5;
    int lane = threadIdx.x & 31;
    if (w >= SS * NP) return;
    int s = w / NP;
    const __nv_bfloat16* feat = f.p[s];
    int e0 = off[w], e1 = off[w + 1];
    float a0 = 0.f, a1 = 0.f, a2 = 0.f, a3 = 0.f;
    for (int e = e0; e < e1; e++) {
        int sn = bsrc[e];
        uint2 u = *(const uint2*)(feat + (size_t)sn * DD + lane * 4);
        __nv_bfloat162 p0 = *(__nv_bfloat162*)&u.x;
        __nv_bfloat162 p1 = *(__nv_bfloat162*)&u.y;
        float2 f0 = __bfloat1622float2(p0), f1 = __bfloat1622float2(p1);
        a0 += f0.x; a1 += f0.y; a2 += f1.x; a3 += f1.y;
    }
    if (e1 > e0) {
        float inv = 1.0f / (float)(e1 - e0);
        a0 *= inv; a1 *= inv; a2 *= inv; a3 *= inv;
    }
    uint2 o;
    *(__nv_bfloat162*)&o.x = __floats2bfloat162_rn(a0, a1);
    *(__nv_bfloat162*)&o.y = __floats2bfloat162_rn(a2, a3);
    *(uint2*)(agg3 + (size_t)w * DD + lane * 4) = o;
}

// ================= streaming bf16 WMMA GEMM (R7 core, slice-batched) =========
#define LDTB 136
#define LDC2 132
#define SMB 34816
#define BG_SMEM (3 * SMB)

struct GemmArgs {
    const __nv_bfloat16* A[6];
    const __nv_bfloat16* B[6];
    const float* bias[6];
    __nv_bfloat16* C[6];
};

__device__ __forceinline__ void cp16(void* s, const void* g) {
    uint32_t sa = (uint32_t)__cvta_generic_to_shared(s);
    asm volatile("cp.async.cg.shared.global [%0], [%1], 16;" :: "r"(sa), "l"(g));
}
__device__ __forceinline__ void tile_load_async(__nv_bfloat16* dstS,
                                                const __nv_bfloat16* srcG, int tid) {
    for (int slot = tid; slot < 2048; slot += 256) {
        int r = slot >> 4;
        int c8 = (slot & 15) * 8;
        cp16(dstS + r * LDTB + c8, srcG + (size_t)r * 128 + c8);
    }
}

__global__ void __launch_bounds__(256, 2)
bf16_gemm(GemmArgs ga, int J, int mtiles) {
    int z = blockIdx.z;
    const __nv_bfloat16* A = ga.A[z];
    const __nv_bfloat16* B = ga.B[z];
    const float* bias = ga.bias[z];
    __nv_bfloat16* C = ga.C[z];

    extern __shared__ char smx[];
    __nv_bfloat16* Bs = (__nv_bfloat16*)smx;
    __nv_bfloat16* Abuf0 = (__nv_bfloat16*)(smx + SMB);
    __nv_bfloat16* Abuf1 = (__nv_bfloat16*)(smx + 2 * SMB);

    int tid = threadIdx.x;
    int warp = tid >> 5;
    int row0 = (warp >> 1) * 32;
    int col0 = (warp & 1) * 64;
    int bn = blockIdx.x * 128;

    int mt = blockIdx.y;
    if (mt >= mtiles) return;

    tile_load_async(Bs, B + (size_t)bn * 128, tid);
    tile_load_async(Abuf0, A + (size_t)mt * 128 * 128, tid);
    asm volatile("cp.async.commit_group;");

    int buf = 0;
    while (mt < mtiles) {
        int nxt = mt + gridDim.y;
        bool pf = (nxt < mtiles);
        __nv_bfloat16* Acur = buf ? Abuf1 : Abuf0;
        __nv_bfloat16* Aalt = buf ? Abuf0 : Abuf1;
        if (pf) {
            tile_load_async(Aalt, A + (size_t)nxt * 128 * 128, tid);
            asm volatile("cp.async.commit_group;");
            asm volatile("cp.async.wait_group 1;");
        } else {
            asm volatile("cp.async.wait_group 0;");
        }
        __syncthreads();

        wmma::fragment<wmma::accumulator, 16, 16, 16, float> acc[2][4];
#pragma unroll
        for (int i = 0; i < 2; i++)
#pragma unroll
            for (int j = 0; j < 4; j++) wmma::fill_fragment(acc[i][j], 0.0f);

#pragma unroll
        for (int k = 0; k < 8; k++) {
            wmma::fragment<wmma::matrix_a, 16, 16, 16, __nv_bfloat16, wmma::row_major> a[2];
            wmma::fragment<wmma::matrix_b, 16, 16, 16, __nv_bfloat16, wmma::col_major> b[4];
#pragma unroll
            for (int i = 0; i < 2; i++)
                wmma::load_matrix_sync(a[i], Acur + (row0 + i * 16) * LDTB + k * 16, LDTB);
#pragma unroll
            for (int j = 0; j < 4; j++)
                wmma::load_matrix_sync(b[j], Bs + (col0 + j * 16) * LDTB + k * 16, LDTB);
#pragma unroll
            for (int i = 0; i < 2; i++)
#pragma unroll
                for (int j = 0; j < 4; j++)
                    wmma::mma_sync(acc[i][j], a[i], b[j], acc[i][j]);
        }
        __syncthreads();

        float* Cs = (float*)Acur;
        int bm = mt * 128;
#pragma unroll
        for (int h = 0; h < 2; h++) {
            if ((warp >> 2) == h) {
                int lr = row0 - h * 64;
#pragma unroll
                for (int i = 0; i < 2; i++)
#pragma unroll
                    for (int j = 0; j < 4; j++)
                        wmma::store_matrix_sync(Cs + (lr + i * 16) * LDC2 + col0 + j * 16,
                                                acc[i][j], LDC2, wmma::mem_row_major);
            }
            __syncthreads();
            for (int slot = tid; slot < 64 * 32; slot += 256) {
                int r = slot >> 5;
                int c4 = (slot & 31) * 4;
                float4 v = *(float4*)(Cs + r * LDC2 + c4);
                if (bias != nullptr) {
                    v.x += bias[bn + c4 + 0];
                    v.y += bias[bn + c4 + 1];
                    v.z += bias[bn + c4 + 2];
                    v.w += bias[bn + c4 + 3];
                }
                int grow = bm + h * 64 + r;
                __nv_bfloat16* crow = C + (size_t)grow * J + bn + c4;
                *(__nv_bfloat162*)(crow)     = __floats2bfloat162_rn(v.x, v.y);
                *(__nv_bfloat162*)(crow + 2) = __floats2bfloat162_rn(v.z, v.w);
            }
            __syncthreads();
        }
        mt = nxt;
        buf ^= 1;
    }
}

// ---------------- GRU math ----------------
__device__ __forceinline__ float tanhapx(float x) {
    float y;
    asm("tanh.approx.f32 %0, %1;" : "=f"(y) : "f"(x));
    return y;
}
__device__ __forceinline__ float sigf(float x) {
    return 0.5f * tanhapx(0.5f * x) + 0.5f;
}
__device__ __forceinline__ float4 ldbf4(const __nv_bfloat16* p) {
    uint2 u = *(const uint2*)p;
    __nv_bfloat162 a = *(__nv_bfloat162*)&u.x;
    __nv_bfloat162 b = *(__nv_bfloat162*)&u.y;
    float2 fa = __bfloat1622float2(a), fb = __bfloat1622float2(b);
    return make_float4(fa.x, fa.y, fb.x, fb.y);
}
__device__ __forceinline__ void stbf4(__nv_bfloat16* p, float4 v) {
    uint2 u;
    *(__nv_bfloat162*)&u.x = __floats2bfloat162_rn(v.x, v.y);
    *(__nv_bfloat162*)&u.y = __floats2bfloat162_rn(v.z, v.w);
    *(uint2*)p = u;
}
__device__ __forceinline__ float4 gru4(float4 ir, float4 iz, float4 in4,
                                       float4 hr, float4 hz, float4 hn, float4 h) {
    float4 o;
    { float r = sigf(ir.x + hr.x), z = sigf(iz.x + hz.x);
      float nn = tanhapx(in4.x + r * hn.x); o.x = (1.f - z) * nn + z * h.x; }
    { float r = sigf(ir.y + hr.y), z = sigf(iz.y + hz.y);
      float nn = tanhapx(in4.y + r * hn.y); o.y = (1.f - z) * nn + z * h.y; }
    { float r = sigf(ir.z + hr.z), z = sigf(iz.z + hz.z);
      float nn = tanhapx(in4.z + r * hn.z); o.z = (1.f - z) * nn + z * h.z; }
    { float r = sigf(ir.w + hr.w), z = sigf(iz.w + hz.w);
      float nn = tanhapx(in4.w + r * hn.w); o.w = (1.f - z) * nn + z * h.w; }
    return o;
}

// i=0: hb3[s] = GRU(gi3[s], gh3[s], hold=xb)
__global__ void gru3_first_kernel(const __nv_bfloat16* __restrict__ gi3,
                                  const __nv_bfloat16* __restrict__ gh3,
                                  const __nv_bfloat16* __restrict__ xb,
                                  __nv_bfloat16* __restrict__ hb3) {
    int idx = blockIdx.x * blockDim.x + threadIdx.x;
    if (idx >= NN * 32) return;
    int s = blockIdx.y;
    int n = idx >> 5;
    int c = (idx & 31) * 4;
    const __nv_bfloat16* gir = gi3 + (size_t)s * NP * 384 + (size_t)n * 384;
    const __nv_bfloat16* ghr = gh3 + (size_t)s * NP * 384 + (size_t)n * 384;
    float4 h = ldbf4(xb + (size_t)n * 128 + c);
    float4 o = gru4(ldbf4(gir + c), ldbf4(gir + 128 + c), ldbf4(gir + 256 + c),
                    ldbf4(ghr + c), ldbf4(ghr + 128 + c), ldbf4(ghr + 256 + c), h);
    stbf4(hb3 + (size_t)s * NP * 128 + (size_t)n * 128 + c, o);
}

// i=1: xb = mean_s GRU(gi3[s], gh3[s], hold=hb3[s])
__global__ void gru3_final_kernel(const __nv_bfloat16* __restrict__ gi3,
                                  const __nv_bfloat16* __restrict__ gh3,
                                  const __nv_bfloat16* __restrict__ hb3,
                                  __nv_bfloat16* __restrict__ xb) {
    int idx = blockIdx.x * blockDim.x + threadIdx.x;
    if (idx >= NN * 32) return;
    int n = idx >> 5;
    int c = (idx & 31) * 4;
    float4 xv = make_float4(0.f, 0.f, 0.f, 0.f);
#pragma unroll
    for (int s = 0; s < SS; s++) {
        const __nv_bfloat16* gir = gi3 + (size_t)s * NP * 384 + (size_t)n * 384;
        const __nv_bfloat16* ghr = gh3 + (size_t)s * NP * 384 + (size_t)n * 384;
        float4 h = ldbf4(hb3 + (size_t)s * NP * 128 + (size_t)n * 128 + c);
        float4 o = gru4(ldbf4(gir + c), ldbf4(gir + 128 + c), ldbf4(gir + 256 + c),
                        ldbf4(ghr + c), ldbf4(ghr + 128 + c), ldbf4(ghr + 256 + c), h);
        xv.x += o.x; xv.y += o.y; xv.z += o.z; xv.w += o.w;
    }
    xv.x *= (1.0f / 3.0f); xv.y *= (1.0f / 3.0f);
    xv.z *= (1.0f / 3.0f); xv.w *= (1.0f / 3.0f);
    stbf4(xb + (size_t)n * 128 + c, xv);
}

// ---------------- pooling / MLP ----------------
__global__ void cnt_kernel(const int* __restrict__ batch, float* __restrict__ cnt, int n) {
    int i = blockIdx.x * blockDim.x + threadIdx.x;
    if (i < n) atomicAdd(&cnt[batch[i]], 1.0f);
}
__global__ void pool_kernel(const __nv_bfloat16* __restrict__ xb, const int* __restrict__ batch,
                            float* __restrict__ pool) {
    int idx = blockIdx.x * blockDim.x + threadIdx.x;
    if (idx >= NN * 32) return;
    int n = idx >> 5;
    int c = (idx & 31) * 4;
    int g = batch[n];
    float4 v = ldbf4(xb + (size_t)n * 128 + c);
    float* o = pool + (size_t)g * 128 + c;
    asm volatile("red.global.add.v4.f32 [%0], {%1,%2,%3,%4};"
                 :: "l"(o), "f"(v.x), "f"(v.y), "f"(v.z), "f"(v.w) : "memory");
}
__global__ void mlp_kernel(const float* __restrict__ pool, const float* __restrict__ cnt,
                           const float* __restrict__ pt,
                           const float* __restrict__ fc1w, const float* __restrict__ fc1b,
                           const float* __restrict__ fc2w, const float* __restrict__ fc2b,
                           const float* __restrict__ fclw, const float* __restrict__ fclb,
                           float* __restrict__ out) {
    __shared__ float h1[GG * 80];
    __shared__ float h2[GG * 80];
    int tid = threadIdx.x;
    for (int t = tid; t < GG * 80; t += blockDim.x) {
        int g = t / 80, j = t - (t / 80) * 80;
        float ic = 1.0f / fmaxf(cnt[g], 1.0f);
        float acc = fc1b[j];
        const float* w = fc1w + j * 129;
        const float* p = pool + g * 128;
        for (int k = 0; k < 128; k++) acc = fmaf(p[k] * ic, w[k], acc);
        acc = fmaf(pt[g], w[128], acc);
        h1[t] = acc > 0.f ? acc : 0.01f * acc;
    }
    __syncthreads();
    for (int t = tid; t < GG * 80; t += blockDim.x) {
        int g = t / 80, j = t - (t / 80) * 80;
        float acc = fc2b[j];
        const float* w = fc2w + j * 80;
        const float* hh = h1 + g * 80;
        for (int k = 0; k < 80; k++) acc = fmaf(hh[k], w[k], acc);
        h2[t] = acc > 0.f ? acc : 0.01f * acc;
    }
    __syncthreads();
    for (int t = tid; t < GG * OUTD; t += blockDim.x) {
        int g = t / OUTD, o = t - (t / OUTD) * OUTD;
        float acc = fclb[o];
        const float* w = fclw + o * 80;
        const float* hh = h2 + g * 80;
        for (int k = 0; k < 80; k++) acc = fmaf(hh[k], w[k], acc);
        out[t] = acc;
    }
}

// ---------------- host launcher ----------------
extern "C" void kernel_launch(void* const* d_in, const int* in_sizes, int n_in,
                              void* d_out, int out_size) {
    (void)in_sizes; (void)n_in; (void)out_size;
    const float* x     = (const float*)d_in[0];
    const int*   eidx  = (const int*)d_in[1];
    const int*   eattr = (const int*)d_in[2];
    const int*   batch = (const int*)d_in[3];
    const float* pt    = (const float*)d_in[4];
    const float* W     = (const float*)d_in[5];
    const float* wih   = (const float*)d_in[6];
    const float* whh   = (const float*)d_in[7];
    const float* bih   = (const float*)d_in[8];
    const float* bhh   = (const float*)d_in[9];
    const float* fc1w  = (const float*)d_in[10];
    const float* fc1b  = (const float*)d_in[11];
    const float* fc2w  = (const float*)d_in[12];
    const float* fc2b  = (const float*)d_in[13];
    const float* fclw  = (const float*)d_in[14];
    const float* fclb  = (const float*)d_in[15];
    float* out = (float*)d_out;

    const int* src = eidx;
    const int* dst = eidx + EE;

    float *poolp, *cntp;
    __nv_bfloat16 *xb, *hb3, *agg3, *gi3, *gh3, *wcb, *wihb, *whhb, *Wb;
    int *bsrcp, *ecntp, *ecurp, *eoffp;
    cudaGetSymbolAddress((void**)&xb,    g_xb);
    cudaGetSymbolAddress((void**)&hb3,   g_hb3);
    cudaGetSymbolAddress((void**)&agg3,  g_agg3);
    cudaGetSymbolAddress((void**)&gi3,   g_gi3);
    cudaGetSymbolAddress((void**)&gh3,   g_gh3);
    cudaGetSymbolAddress((void**)&wcb,   g_wcb);
    cudaGetSymbolAddress((void**)&wihb,  g_wihb);
    cudaGetSymbolAddress((void**)&whhb,  g_whhb);
    cudaGetSymbolAddress((void**)&Wb,    g_Wb);
    cudaGetSymbolAddress((void**)&poolp, g_pool);
    cudaGetSymbolAddress((void**)&cntp,  g_cnt);
    cudaGetSymbolAddress((void**)&bsrcp, g_bsrc);
    cudaGetSymbolAddress((void**)&ecntp, g_ecnt);
    cudaGetSymbolAddress((void**)&ecurp, g_ecur);
    cudaGetSymbolAddress((void**)&eoffp, g_eoff);

    cudaFuncSetAttribute(bf16_gemm, cudaFuncAttributeMaxDynamicSharedMemorySize, BG_SMEM);

    const int TB = 256;
    dim3 g3(3, 32, 3);   // 288 CTAs, each streams ~25 M-tiles

    // side stream + events for fork/join (host objects; created per call)
    cudaStream_t s2;
    cudaStreamCreateWithFlags(&s2, cudaStreamNonBlocking);
    cudaEvent_t evF[4], evJ[4];
    for (int k = 0; k < 4; k++) {
        cudaEventCreateWithFlags(&evF[k], cudaEventDisableTiming);
        cudaEventCreateWithFlags(&evJ[k], cudaEventDisableTiming);
    }

    // ---- prologue (stream 0) ----
    copy_pad_kernel<<<(NP * 32 + TB - 1) / TB, TB>>>(x, xb);                    // 0
    cvt_bf16_kernel<<<(SS * 384 * 32 + TB - 1) / TB, TB>>>(whh, whhb,
                                                           SS * 384 * 32);      // 1
    zero2_ints<<<(NPS + TB - 1) / TB, TB>>>(ecntp, ecurp, NPS);                 // 2
    // 3 (PROFILED): gh GEMM for superstep (0,0)
    {
        GemmArgs ga;
        for (int s = 0; s < 3; s++) {
            ga.A[s] = xb;
            ga.B[s] = whhb + (size_t)s * 384 * 128;
            ga.bias[s] = bhh + s * 384;
            ga.C[s] = gh3 + (size_t)s * NP * 384;
        }
        bf16_gemm<<<g3, TB, BG_SMEM>>>(ga, 384, M_TILES);
    }
    cvt_bf16_kernel<<<(SS * 384 * 32 + TB - 1) / TB, TB>>>(wih, wihb, SS * 384 * 32);
    cvt_bf16_kernel<<<(SS * 2 * 128 * 32 + TB - 1) / TB, TB>>>(W, Wb, SS * 2 * 128 * 32);
    ecount_kernel<<<(EE + TB - 1) / TB, TB>>>(dst, eattr, ecntp, EE);
    scan_kernel<<<1, 1024>>>(ecntp, eoffp, NPS);
    fill_kernel<<<(EE + TB - 1) / TB, TB>>>(src, dst, eattr, eoffp, ecurp, bsrcp, EE);
    {
        GemmArgs ga;
        for (int z = 0; z < 6; z++) {
            int s = z / 2, i = z % 2;
            ga.A[z] = wihb + (size_t)s * 384 * 128;
            ga.B[z] = Wb + (size_t)(s * 2 + i) * 128 * 128;
            ga.bias[z] = nullptr;
            ga.C[z] = wcb + (size_t)(s * 2 + i) * 384 * 128;
        }
        bf16_gemm<<<dim3(1, 3, 6), TB, BG_SMEM>>>(ga, 128, 3);
    }

    // ---- main loop: 4 supersteps, gh-GEMM (stream 0) ∥ gather+gi-GEMM (s2) ----
    int step = 0;
    for (int pass = 0; pass < 2; pass++) {
        for (int i = 0; i < 2; i++, step++) {
            // fork
            cudaEventRecord(evF[step], 0);
            cudaStreamWaitEvent(s2, evF[step], 0);

            // s2: gather + gi GEMM
            Feat3 f;
            if (i == 0) { f.p[0] = xb; f.p[1] = xb; f.p[2] = xb; }
            else {
                f.p[0] = hb3;
                f.p[1] = hb3 + (size_t)NP * 128;
                f.p[2] = hb3 + (size_t)2 * NP * 128;
            }
            gather3_kernel<<<(SS * NP * 32 + TB - 1) / TB, TB, 0, s2>>>(
                eoffp, bsrcp, f, agg3);
            {
                GemmArgs ga;
                for (int s = 0; s < 3; s++) {
                    ga.A[s] = agg3 + (size_t)s * NP * 128;
                    ga.B[s] = wcb + (size_t)(s * 2 + i) * 384 * 128;
                    ga.bias[s] = bih + s * 384;
                    ga.C[s] = gi3 + (size_t)s * NP * 384;
                }
                bf16_gemm<<<g3, TB, BG_SMEM, s2>>>(ga, 384, M_TILES);
            }

            // stream 0: gh GEMM (superstep 0's was already launched in prologue)
            if (step > 0) {
                GemmArgs ga;
                for (int s = 0; s < 3; s++) {
                    ga.A[s] = (i == 0) ? xb : (hb3 + (size_t)s * NP * 128);
                    ga.B[s] = whhb + (size_t)s * 384 * 128;
                    ga.bias[s] = bhh + s * 384;
                    ga.C[s] = gh3 + (size_t)s * NP * 384;
                }
                bf16_gemm<<<g3, TB, BG_SMEM>>>(ga, 384, M_TILES);
            }

            // join
            cudaEventRecord(evJ[step], s2);
            cudaStreamWaitEvent(0, evJ[step], 0);

            // GRU
            if (i == 0)
                gru3_first_kernel<<<dim3((NN * 32 + TB - 1) / TB, 3), TB>>>(
                    gi3, gh3, xb, hb3);
            else
                gru3_final_kernel<<<(NN * 32 + TB - 1) / TB, TB>>>(gi3, gh3, hb3, xb);
        }
    }

    // ---- pooling + MLP ----
    zero_kernel<<<(GG * DD / 4 + TB - 1) / TB, TB>>>(poolp, GG * DD / 4);
    zero_kernel<<<1, GG / 4>>>(cntp, GG / 4);
    cnt_kernel<<<(NN + TB - 1) / TB, TB>>>(batch, cntp, NN);
    pool_kernel<<<(NN * 32 + TB - 1) / TB, TB>>>(xb, batch, poolp);
    mlp_kernel<<<1, 256>>>(poolp, cntp, pt, fc1w, fc1b, fc2w, fc2b, fclw, fclb, out);

    // cleanup host objects (skip during capture; graph holds no references, but be safe)
    cudaStreamCaptureStatus cap = cudaStreamCaptureStatusNone;
    cudaStreamIsCapturing(0, &cap);
    if (cap == cudaStreamCaptureStatusNone) {
        for (int k = 0; k < 4; k++) { cudaEventDestroy(evF[k]); cudaEventDestroy(evJ[k]); }
        cudaStreamDestroy(s2);
    }
}

// round 11
// speedup vs baseline: 1.1864x; 1.1864x over previous
#include <cuda_runtime.h>
#include <cuda_bf16.h>
#include <math.h>
#include <stdint.h>

#define NN 100000
#define NP 100096
#define EE 600000
#define DD 128
#define SS 3
#define GG 64
#define OUTD 2
#define NPS (SS * NP)
#define M_TILES (NP / 128)        // 782

// ---------------- device scratch ----------------
__device__ __nv_bfloat16 g_xb[NP * DD];
__device__ __nv_bfloat16 g_hb3[SS * NP * DD];
__device__ __nv_bfloat16 g_agg3[SS * NP * DD];
__device__ __nv_bfloat16 g_gi3[SS * NP * 3 * DD];
__device__ __nv_bfloat16 g_gh3[SS * NP * 3 * DD];
__device__ __nv_bfloat16 g_wcb[SS * 2 * 3 * DD * DD];
__device__ __nv_bfloat16 g_wihb[SS * 3 * DD * DD];
__device__ __nv_bfloat16 g_whhb[SS * 3 * DD * DD];
__device__ __nv_bfloat16 g_Wb[SS * 2 * DD * DD];
__device__ float g_pool[GG * DD];
__device__ float g_cnt[GG];
__device__ int   g_bsrc[EE];
__device__ int   g_ecnt[NPS];
__device__ int   g_ecur[NPS];
__device__ int   g_eoff[NPS + 1];

// ---------------- tiny utils ----------------
__global__ void zero_kernel(float* __restrict__ p, int n4) {
    int i = blockIdx.x * blockDim.x + threadIdx.x;
    if (i < n4) ((float4*)p)[i] = make_float4(0.f, 0.f, 0.f, 0.f);
}
__global__ void copy_pad_kernel(const float* __restrict__ x, __nv_bfloat16* __restrict__ xb) {
    int i = blockIdx.x * blockDim.x + threadIdx.x;
    if (i >= NP * 32) return;
    int n = i >> 5;
    float4 v = make_float4(0.f, 0.f, 0.f, 0.f);
    if (n < NN) v = ((const float4*)x)[i];
    *(__nv_bfloat162*)(xb + (size_t)i * 4)     = __floats2bfloat162_rn(v.x, v.y);
    *(__nv_bfloat162*)(xb + (size_t)i * 4 + 2) = __floats2bfloat162_rn(v.z, v.w);
}
__global__ void cvt_bf16_kernel(const float* __restrict__ src,
                                __nv_bfloat16* __restrict__ dst, int n4) {
    int i = blockIdx.x * blockDim.x + threadIdx.x;
    if (i >= n4) return;
    float4 v = ((const float4*)src)[i];
    *(__nv_bfloat162*)(dst + (size_t)i * 4)     = __floats2bfloat162_rn(v.x, v.y);
    *(__nv_bfloat162*)(dst + (size_t)i * 4 + 2) = __floats2bfloat162_rn(v.z, v.w);
}
__global__ void zero2_ints(int* __restrict__ a, int* __restrict__ b, int n) {
    int i = blockIdx.x * blockDim.x + threadIdx.x;
    if (i < n) { a[i] = 0; b[i] = 0; }
}

// ---------------- CSR build ----------------
__global__ void ecount_kernel(const int* __restrict__ dst, const int* __restrict__ attr,
                              int* __restrict__ cnt, int E) {
    int e = blockIdx.x * blockDim.x + threadIdx.x;
    if (e < E) atomicAdd(&cnt[attr[e] * NP + dst[e]], 1);
}
__global__ void scan_kernel(const int* __restrict__ cnt, int* __restrict__ off, int n) {
    __shared__ int ssum[1024];
    int t = threadIdx.x;
    int per = (n + 1023) / 1024;
    int b0 = t * per;
    int b1 = b0 + per; if (b1 > n) b1 = n; if (b0 > n) b0 = n;
    int s = 0;
    for (int i = b0; i < b1; i++) s += cnt[i];
    ssum[t] = s;
    __syncthreads();
    for (int d = 1; d < 1024; d <<= 1) {
        int v = (t >= d) ? ssum[t - d] : 0;
        __syncthreads();
        ssum[t] += v;
        __syncthreads();
    }
    int run = (t == 0) ? 0 : ssum[t - 1];
    if (t == 1023) off[n] = ssum[1023];
    for (int i = b0; i < b1; i++) { off[i] = run; run += cnt[i]; }
}
__global__ void fill_kernel(const int* __restrict__ src, const int* __restrict__ dst,
                            const int* __restrict__ attr, const int* __restrict__ off,
                            int* __restrict__ cur, int* __restrict__ bsrc, int E) {
    int e = blockIdx.x * blockDim.x + threadIdx.x;
    if (e >= E) return;
    int idx = attr[e] * NP + dst[e];
    int pos = off[idx] + atomicAdd(&cur[idx], 1);
    bsrc[pos] = src[e];
}

// ---------------- gather all 3 types ----------------
struct Feat3 { const __nv_bfloat16* p[3]; };

__global__ void gather3_kernel(const int* __restrict__ off, const int* __restrict__ bsrc,
                               Feat3 f, __nv_bfloat16* __restrict__ agg3) {
    int w = (blockIdx.x * blockDim.x + threadIdx.x) >> 5;
    int lane = threadIdx.x & 31;
    if (w >= SS * NP) return;
    int s = w / NP;
    const __nv_bfloat16* feat = f.p[s];
    int e0 = off[w], e1 = off[w + 1];
    float a0 = 0.f, a1 = 0.f, a2 = 0.f, a3 = 0.f;
    for (int e = e0; e < e1; e++) {
        int sn = bsrc[e];
        uint2 u = *(const uint2*)(feat + (size_t)sn * DD + lane * 4);
        __nv_bfloat162 p0 = *(__nv_bfloat162*)&u.x;
        __nv_bfloat162 p1 = *(__nv_bfloat162*)&u.y;
        float2 f0 = __bfloat1622float2(p0), f1 = __bfloat1622float2(p1);
        a0 += f0.x; a1 += f0.y; a2 += f1.x; a3 += f1.y;
    }
    if (e1 > e0) {
        float inv = 1.0f / (float)(e1 - e0);
        a0 *= inv; a1 *= inv; a2 *= inv; a3 *= inv;
    }
    uint2 o;
    *(__nv_bfloat162*)&o.x = __floats2bfloat162_rn(a0, a1);
    *(__nv_bfloat162*)&o.y = __floats2bfloat162_rn(a2, a3);
    *(uint2*)(agg3 + (size_t)w * DD + lane * 4) = o;
}

// ========== weights-stationary streaming GEMM (raw mma.sync, bf16) ==========
// C[M,J] = A[M,128] @ B[J,128]^T + bias.  CTA: 128(M) x 64(N), 8 warps (32x32).
// B fragments live in registers for the CTA's whole M-stream.
#define LDTB 136
#define SMB_B (64 * LDTB * 2)        // 17408
#define SMB_A (128 * LDTB * 2)       // 34816
#define BG_SMEM (SMB_B + 2 * SMB_A)  // 87040

struct GemmArgs {
    const __nv_bfloat16* A[6];
    const __nv_bfloat16* B[6];
    const float* bias[6];
    __nv_bfloat16* C[6];
};

__device__ __forceinline__ void cp16(void* s, const void* g) {
    uint32_t sa = (uint32_t)__cvta_generic_to_shared(s);
    asm volatile("cp.async.cg.shared.global [%0], [%1], 16;" :: "r"(sa), "l"(g));
}
__device__ __forceinline__ void ldm_x4(uint32_t* r, const __nv_bfloat16* p) {
    uint32_t sa = (uint32_t)__cvta_generic_to_shared(p);
    asm volatile("ldmatrix.sync.aligned.m8n8.x4.shared.b16 {%0,%1,%2,%3}, [%4];"
                 : "=r"(r[0]), "=r"(r[1]), "=r"(r[2]), "=r"(r[3]) : "r"(sa));
}
__device__ __forceinline__ void ldm_x2(uint32_t* r, const __nv_bfloat16* p) {
    uint32_t sa = (uint32_t)__cvta_generic_to_shared(p);
    asm volatile("ldmatrix.sync.aligned.m8n8.x2.shared.b16 {%0,%1}, [%2];"
                 : "=r"(r[0]), "=r"(r[1]) : "r"(sa));
}
__device__ __forceinline__ void mma16816(float* c, const uint32_t* a, const uint32_t* b) {
    asm volatile(
        "mma.sync.aligned.m16n8k16.row.col.f32.bf16.bf16.f32 "
        "{%0,%1,%2,%3}, {%4,%5,%6,%7}, {%8,%9}, {%0,%1,%2,%3};"
        : "+f"(c[0]), "+f"(c[1]), "+f"(c[2]), "+f"(c[3])
        : "r"(a[0]), "r"(a[1]), "r"(a[2]), "r"(a[3]), "r"(b[0]), "r"(b[1]));
}

__global__ void __launch_bounds__(256, 2)
bf16_gemm(GemmArgs ga, int J, int mtiles) {
    int z = blockIdx.z;
    const __nv_bfloat16* A = ga.A[z];
    const __nv_bfloat16* B = ga.B[z];
    const float* bias = ga.bias[z];
    __nv_bfloat16* C = ga.C[z];

    extern __shared__ char smx[];
    __nv_bfloat16* Bs = (__nv_bfloat16*)smx;
    __nv_bfloat16* Abuf0 = (__nv_bfloat16*)(smx + SMB_B);
    __nv_bfloat16* Abuf1 = (__nv_bfloat16*)(smx + SMB_B + SMB_A);

    int tid = threadIdx.x;
    int warp = tid >> 5;
    int lane = tid & 31;
    int mb = (warp >> 1) * 32;      // m band in [0,128)
    int nb = (warp & 1) * 32;       // n band in [0,64)
    int bn = blockIdx.x * 64;

    int mt = blockIdx.y;
    if (mt >= mtiles) return;

    // B tile: 64 rows x 128 cols
    for (int slot = tid; slot < 64 * 16; slot += 256) {
        int r = slot >> 4;
        int c8 = (slot & 15) * 8;
        cp16(Bs + r * LDTB + c8, B + (size_t)(bn + r) * 128 + c8);
    }
    asm volatile("cp.async.commit_group;");
    // first A tile
    for (int slot = tid; slot < 128 * 16; slot += 256) {
        int r = slot >> 4;
        int c8 = (slot & 15) * 8;
        cp16(Abuf0 + r * LDTB + c8, A + (size_t)mt * 128 * 128 + (size_t)r * 128 + c8);
    }
    asm volatile("cp.async.commit_group;");
    asm volatile("cp.async.wait_group 1;");   // B ready
    __syncthreads();

    // resident B fragments: 4 n8-tiles x 8 k16-tiles x 2 regs
    uint32_t bf[4][8][2];
    {
        int lr = lane & 7;
        int ls = (lane >> 3) & 1;
#pragma unroll
        for (int nt = 0; nt < 4; nt++)
#pragma unroll
            for (int kt = 0; kt < 8; kt++)
                ldm_x2(bf[nt][kt], Bs + (nb + nt * 8 + lr) * LDTB + kt * 16 + ls * 8);
    }

    int buf = 0;
    while (mt < mtiles) {
        int nxt = mt + gridDim.y;
        bool pf = (nxt < mtiles);
        __nv_bfloat16* Acur = buf ? Abuf1 : Abuf0;
        __nv_bfloat16* Aalt = buf ? Abuf0 : Abuf1;
        if (pf) {
            for (int slot = tid; slot < 128 * 16; slot += 256) {
                int r = slot >> 4;
                int c8 = (slot & 15) * 8;
                cp16(Aalt + r * LDTB + c8,
                     A + (size_t)nxt * 128 * 128 + (size_t)r * 128 + c8);
            }
            asm volatile("cp.async.commit_group;");
            asm volatile("cp.async.wait_group 1;");
        } else {
            asm volatile("cp.async.wait_group 0;");
        }
        __syncthreads();

        float acc[2][4][4];
#pragma unroll
        for (int i = 0; i < 2; i++)
#pragma unroll
            for (int nt = 0; nt < 4; nt++)
#pragma unroll
                for (int e = 0; e < 4; e++) acc[i][nt][e] = 0.f;

        int q = lane >> 3;
        int arow = (q & 1) * 8 + (lane & 7);
        int acol = (q >> 1) * 8;
#pragma unroll
        for (int kt = 0; kt < 8; kt++) {
            uint32_t a[2][4];
#pragma unroll
            for (int i = 0; i < 2; i++)
                ldm_x4(a[i], Acur + (mb + i * 16 + arow) * LDTB + kt * 16 + acol);
#pragma unroll
            for (int i = 0; i < 2; i++)
#pragma unroll
                for (int nt = 0; nt < 4; nt++)
                    mma16816(acc[i][nt], a[i], bf[nt][kt]);
        }

        // epilogue: direct bf16 stores with bias
        int bm = mt * 128;
#pragma unroll
        for (int i = 0; i < 2; i++) {
#pragma unroll
            for (int nt = 0; nt < 4; nt++) {
                int r0 = bm + mb + i * 16 + (lane >> 2);
                int cc = bn + nb + nt * 8 + ((lane & 3) << 1);
                float b0v = 0.f, b1v = 0.f;
                if (bias != nullptr) { b0v = bias[cc]; b1v = bias[cc + 1]; }
                *(__nv_bfloat162*)(C + (size_t)r0 * J + cc) =
                    __floats2bfloat162_rn(acc[i][nt][0] + b0v, acc[i][nt][1] + b1v);
                *(__nv_bfloat162*)(C + (size_t)(r0 + 8) * J + cc) =
                    __floats2bfloat162_rn(acc[i][nt][2] + b0v, acc[i][nt][3] + b1v);
            }
        }
        __syncthreads();   // all reads of Acur done before it is prefetch-target again
        mt = nxt;
        buf ^= 1;
    }
}

// ---------------- GRU math ----------------
__device__ __forceinline__ float tanhapx(float x) {
    float y;
    asm("tanh.approx.f32 %0, %1;" : "=f"(y) : "f"(x));
    return y;
}
__device__ __forceinline__ float sigf(float x) {
    return 0.5f * tanhapx(0.5f * x) + 0.5f;
}
__device__ __forceinline__ float4 ldbf4(const __nv_bfloat16* p) {
    uint2 u = *(const uint2*)p;
    __nv_bfloat162 a = *(__nv_bfloat162*)&u.x;
    __nv_bfloat162 b = *(__nv_bfloat162*)&u.y;
    float2 fa = __bfloat1622float2(a), fb = __bfloat1622float2(b);
    return make_float4(fa.x, fa.y, fb.x, fb.y);
}
__device__ __forceinline__ void stbf4(__nv_bfloat16* p, float4 v) {
    uint2 u;
    *(__nv_bfloat162*)&u.x = __floats2bfloat162_rn(v.x, v.y);
    *(__nv_bfloat162*)&u.y = __floats2bfloat162_rn(v.z, v.w);
    *(uint2*)p = u;
}
__device__ __forceinline__ float4 gru4(float4 ir, float4 iz, float4 in4,
                                       float4 hr, float4 hz, float4 hn, float4 h) {
    float4 o;
    { float r = sigf(ir.x + hr.x), z = sigf(iz.x + hz.x);
      float nn = tanhapx(in4.x + r * hn.x); o.x = (1.f - z) * nn + z * h.x; }
    { float r = sigf(ir.y + hr.y), z = sigf(iz.y + hz.y);
      float nn = tanhapx(in4.y + r * hn.y); o.y = (1.f - z) * nn + z * h.y; }
    { float r = sigf(ir.z + hr.z), z = sigf(iz.z + hz.z);
      float nn = tanhapx(in4.z + r * hn.z); o.z = (1.f - z) * nn + z * h.z; }
    { float r = sigf(ir.w + hr.w), z = sigf(iz.w + hz.w);
      float nn = tanhapx(in4.w + r * hn.w); o.w = (1.f - z) * nn + z * h.w; }
    return o;
}

__global__ void gru3_first_kernel(const __nv_bfloat16* __restrict__ gi3,
                                  const __nv_bfloat16* __restrict__ gh3,
                                  const __nv_bfloat16* __restrict__ xb,
                                  __nv_bfloat16* __restrict__ hb3) {
    int idx = blockIdx.x * blockDim.x + threadIdx.x;
    if (idx >= NN * 32) return;
    int s = blockIdx.y;
    int n = idx >> 5;
    int c = (idx & 31) * 4;
    const __nv_bfloat16* gir = gi3 + (size_t)s * NP * 384 + (size_t)n * 384;
    const __nv_bfloat16* ghr = gh3 + (size_t)s * NP * 384 + (size_t)n * 384;
    float4 h = ldbf4(xb + (size_t)n * 128 + c);
    float4 o = gru4(ldbf4(gir + c), ldbf4(gir + 128 + c), ldbf4(gir + 256 + c),
                    ldbf4(ghr + c), ldbf4(ghr + 128 + c), ldbf4(ghr + 256 + c), h);
    stbf4(hb3 + (size_t)s * NP * 128 + (size_t)n * 128 + c, o);
}

__global__ void gru3_final_kernel(const __nv_bfloat16* __restrict__ gi3,
                                  const __nv_bfloat16* __restrict__ gh3,
                                  const __nv_bfloat16* __restrict__ hb3,
                                  __nv_bfloat16* __restrict__ xb) {
    int idx = blockIdx.x * blockDim.x + threadIdx.x;
    if (idx >= NN * 32) return;
    int n = idx >> 5;
    int c = (idx & 31) * 4;
    float4 xv = make_float4(0.f, 0.f, 0.f, 0.f);
#pragma unroll
    for (int s = 0; s < SS; s++) {
        const __nv_bfloat16* gir = gi3 + (size_t)s * NP * 384 + (size_t)n * 384;
        const __nv_bfloat16* ghr = gh3 + (size_t)s * NP * 384 + (size_t)n * 384;
        float4 h = ldbf4(hb3 + (size_t)s * NP * 128 + (size_t)n * 128 + c);
        float4 o = gru4(ldbf4(gir + c), ldbf4(gir + 128 + c), ldbf4(gir + 256 + c),
                        ldbf4(ghr + c), ldbf4(ghr + 128 + c), ldbf4(ghr + 256 + c), h);
        xv.x += o.x; xv.y += o.y; xv.z += o.z; xv.w += o.w;
    }
    xv.x *= (1.0f / 3.0f); xv.y *= (1.0f / 3.0f);
    xv.z *= (1.0f / 3.0f); xv.w *= (1.0f / 3.0f);
    stbf4(xb + (size_t)n * 128 + c, xv);
}

// ---------------- pooling / MLP ----------------
__global__ void cnt_kernel(const int* __restrict__ batch, float* __restrict__ cnt, int n) {
    int i = blockIdx.x * blockDim.x + threadIdx.x;
    if (i < n) atomicAdd(&cnt[batch[i]], 1.0f);
}
__global__ void pool_kernel(const __nv_bfloat16* __restrict__ xb, const int* __restrict__ batch,
                            float* __restrict__ pool) {
    int idx = blockIdx.x * blockDim.x + threadIdx.x;
    if (idx >= NN * 32) return;
    int n = idx >> 5;
    int c = (idx & 31) * 4;
    int g = batch[n];
    float4 v = ldbf4(xb + (size_t)n * 128 + c);
    float* o = pool + (size_t)g * 128 + c;
    asm volatile("red.global.add.v4.f32 [%0], {%1,%2,%3,%4};"
                 :: "l"(o), "f"(v.x), "f"(v.y), "f"(v.z), "f"(v.w) : "memory");
}
__global__ void mlp_kernel(const float* __restrict__ pool, const float* __restrict__ cnt,
                           const float* __restrict__ pt,
                           const float* __restrict__ fc1w, const float* __restrict__ fc1b,
                           const float* __restrict__ fc2w, const float* __restrict__ fc2b,
                           const float* __restrict__ fclw, const float* __restrict__ fclb,
                           float* __restrict__ out) {
    __shared__ float h1[GG * 80];
    __shared__ float h2[GG * 80];
    int tid = threadIdx.x;
    for (int t = tid; t < GG * 80; t += blockDim.x) {
        int g = t / 80, j = t - (t / 80) * 80;
        float ic = 1.0f / fmaxf(cnt[g], 1.0f);
        float acc = fc1b[j];
        const float* w = fc1w + j * 129;
        const float* p = pool + g * 128;
        for (int k = 0; k < 128; k++) acc = fmaf(p[k] * ic, w[k], acc);
        acc = fmaf(pt[g], w[128], acc);
        h1[t] = acc > 0.f ? acc : 0.01f * acc;
    }
    __syncthreads();
    for (int t = tid; t < GG * 80; t += blockDim.x) {
        int g = t / 80, j = t - (t / 80) * 80;
        float acc = fc2b[j];
        const float* w = fc2w + j * 80;
        const float* hh = h1 + g * 80;
        for (int k = 0; k < 80; k++) acc = fmaf(hh[k], w[k], acc);
        h2[t] = acc > 0.f ? acc : 0.01f * acc;
    }
    __syncthreads();
    for (int t = tid; t < GG * OUTD; t += blockDim.x) {
        int g = t / OUTD, o = t - (t / OUTD) * OUTD;
        float acc = fclb[o];
        const float* w = fclw + o * 80;
        const float* hh = h2 + g * 80;
        for (int k = 0; k < 80; k++) acc = fmaf(hh[k], w[k], acc);
        out[t] = acc;
    }
}

// ---------------- host launcher ----------------
extern "C" void kernel_launch(void* const* d_in, const int* in_sizes, int n_in,
                              void* d_out, int out_size) {
    (void)in_sizes; (void)n_in; (void)out_size;
    const float* x     = (const float*)d_in[0];
    const int*   eidx  = (const int*)d_in[1];
    const int*   eattr = (const int*)d_in[2];
    const int*   batch = (const int*)d_in[3];
    const float* pt    = (const float*)d_in[4];
    const float* W     = (const float*)d_in[5];
    const float* wih   = (const float*)d_in[6];
    const float* whh   = (const float*)d_in[7];
    const float* bih   = (const float*)d_in[8];
    const float* bhh   = (const float*)d_in[9];
    const float* fc1w  = (const float*)d_in[10];
    const float* fc1b  = (const float*)d_in[11];
    const float* fc2w  = (const float*)d_in[12];
    const float* fc2b  = (const float*)d_in[13];
    const float* fclw  = (const float*)d_in[14];
    const float* fclb  = (const float*)d_in[15];
    float* out = (float*)d_out;

    const int* src = eidx;
    const int* dst = eidx + EE;

    float *poolp, *cntp;
    __nv_bfloat16 *xb, *hb3, *agg3, *gi3, *gh3, *wcb, *wihb, *whhb, *Wb;
    int *bsrcp, *ecntp, *ecurp, *eoffp;
    cudaGetSymbolAddress((void**)&xb,    g_xb);
    cudaGetSymbolAddress((void**)&hb3,   g_hb3);
    cudaGetSymbolAddress((void**)&agg3,  g_agg3);
    cudaGetSymbolAddress((void**)&gi3,   g_gi3);
    cudaGetSymbolAddress((void**)&gh3,   g_gh3);
    cudaGetSymbolAddress((void**)&wcb,   g_wcb);
    cudaGetSymbolAddress((void**)&wihb,  g_wihb);
    cudaGetSymbolAddress((void**)&whhb,  g_whhb);
    cudaGetSymbolAddress((void**)&Wb,    g_Wb);
    cudaGetSymbolAddress((void**)&poolp, g_pool);
    cudaGetSymbolAddress((void**)&cntp,  g_cnt);
    cudaGetSymbolAddress((void**)&bsrcp, g_bsrc);
    cudaGetSymbolAddress((void**)&ecntp, g_ecnt);
    cudaGetSymbolAddress((void**)&ecurp, g_ecur);
    cudaGetSymbolAddress((void**)&eoffp, g_eoff);

    cudaFuncSetAttribute(bf16_gemm, cudaFuncAttributeMaxDynamicSharedMemorySize, BG_SMEM);

    const int TB = 256;
    dim3 g3(6, 16, 3);   // 288 CTAs = one 2-CTA/SM wave; ~49 M-tiles per CTA

    // ---- prologue ----
    copy_pad_kernel<<<(NP * 32 + TB - 1) / TB, TB>>>(x, xb);                    // 0
    cvt_bf16_kernel<<<(SS * 384 * 32 + TB - 1) / TB, TB>>>(whh, whhb,
                                                           SS * 384 * 32);      // 1
    zero2_ints<<<(NPS + TB - 1) / TB, TB>>>(ecntp, ecurp, NPS);                 // 2
    // 3 (PROFILED): gh GEMM for superstep (0,0)
    {
        GemmArgs ga;
        for (int s = 0; s < 3; s++) {
            ga.A[s] = xb;
            ga.B[s] = whhb + (size_t)s * 384 * 128;
            ga.bias[s] = bhh + s * 384;
            ga.C[s] = gh3 + (size_t)s * NP * 384;
        }
        bf16_gemm<<<g3, TB, BG_SMEM>>>(ga, 384, M_TILES);
    }
    cvt_bf16_kernel<<<(SS * 384 * 32 + TB - 1) / TB, TB>>>(wih, wihb, SS * 384 * 32);
    cvt_bf16_kernel<<<(SS * 2 * 128 * 32 + TB - 1) / TB, TB>>>(W, Wb, SS * 2 * 128 * 32);
    ecount_kernel<<<(EE + TB - 1) / TB, TB>>>(dst, eattr, ecntp, EE);
    scan_kernel<<<1, 1024>>>(ecntp, eoffp, NPS);
    fill_kernel<<<(EE + TB - 1) / TB, TB>>>(src, dst, eattr, eoffp, ecurp, bsrcp, EE);
    // combined weights Wc[s,i] = wih[s] @ W[s,i]^T
    {
        GemmArgs ga;
        for (int z = 0; z < 6; z++) {
            int s = z / 2, i = z % 2;
            ga.A[z] = wihb + (size_t)s * 384 * 128;
            ga.B[z] = Wb + (size_t)(s * 2 + i) * 128 * 128;
            ga.bias[z] = nullptr;
            ga.C[z] = wcb + (size_t)(s * 2 + i) * 384 * 128;
        }
        bf16_gemm<<<dim3(2, 3, 6), TB, BG_SMEM>>>(ga, 128, 3);
    }

    // ---- main loop: 4 supersteps ----
    int step = 0;
    for (int pass = 0; pass < 2; pass++) {
        for (int i = 0; i < 2; i++, step++) {
            Feat3 f;
            if (i == 0) { f.p[0] = xb; f.p[1] = xb; f.p[2] = xb; }
            else {
                f.p[0] = hb3;
                f.p[1] = hb3 + (size_t)NP * 128;
                f.p[2] = hb3 + (size_t)2 * NP * 128;
            }
            gather3_kernel<<<(SS * NP * 32 + TB - 1) / TB, TB>>>(eoffp, bsrcp, f, agg3);
            if (step > 0) {
                GemmArgs ga;
                for (int s = 0; s < 3; s++) {
                    ga.A[s] = (i == 0) ? xb : (hb3 + (size_t)s * NP * 128);
                    ga.B[s] = whhb + (size_t)s * 384 * 128;
                    ga.bias[s] = bhh + s * 384;
                    ga.C[s] = gh3 + (size_t)s * NP * 384;
                }
                bf16_gemm<<<g3, TB, BG_SMEM>>>(ga, 384, M_TILES);
            }
            {
                GemmArgs ga;
                for (int s = 0; s < 3; s++) {
                    ga.A[s] = agg3 + (size_t)s * NP * 128;
                    ga.B[s] = wcb + (size_t)(s * 2 + i) * 384 * 128;
                    ga.bias[s] = bih + s * 384;
                    ga.C[s] = gi3 + (size_t)s * NP * 384;
                }
                bf16_gemm<<<g3, TB, BG_SMEM>>>(ga, 384, M_TILES);
            }
            if (i == 0)
                gru3_first_kernel<<<dim3((NN * 32 + TB - 1) / TB, 3), TB>>>(
                    gi3, gh3, xb, hb3);
            else
                gru3_final_kernel<<<(NN * 32 + TB - 1) / TB, TB>>>(gi3, gh3, hb3, xb);
        }
    }

    // ---- pooling + MLP ----
    zero_kernel<<<(GG * DD / 4 + TB - 1) / TB, TB>>>(poolp, GG * DD / 4);
    zero_kernel<<<1, GG / 4>>>(cntp, GG / 4);
    cnt_kernel<<<(NN + TB - 1) / TB, TB>>>(batch, cntp, NN);
    pool_kernel<<<(NN * 32 + TB - 1) / TB, TB>>>(xb, batch, poolp);
    mlp_kernel<<<1, 256>>>(poolp, cntp, pt, fc1w, fc1b, fc2w, fc2b, fclw, fclb, out);
}

// round 12
// speedup vs baseline: 1.2321x; 1.0385x over previous
#include <cuda_runtime.h>
#include <cuda_bf16.h>
#include <math.h>
#include <stdint.h>

#define NN 100000
#define NP 100096
#define EE 600000
#define DD 128
#define SS 3
#define GG 64
#define OUTD 2
#define NPS (SS * NP)
#define M_TILES (NP / 128)        // 782

// ---------------- device scratch ----------------
__device__ __nv_bfloat16 g_xb[NP * DD];
__device__ __nv_bfloat16 g_hb3[SS * NP * DD];
__device__ __nv_bfloat16 g_agg3[SS * NP * DD];
__device__ __nv_bfloat16 g_gi3[SS * NP * 3 * DD];
__device__ __nv_bfloat16 g_gh3[SS * NP * 3 * DD];
__device__ __nv_bfloat16 g_wcb[SS * 2 * 3 * DD * DD];
__device__ __nv_bfloat16 g_wihb[SS * 3 * DD * DD];
__device__ __nv_bfloat16 g_whhb[SS * 3 * DD * DD];
__device__ __nv_bfloat16 g_Wb[SS * 2 * DD * DD];
__device__ float g_pool[GG * DD];
__device__ float g_cnt[GG];
__device__ int   g_bsrc[EE];
__device__ int   g_ecnt[NPS];
__device__ int   g_ecur[NPS];
__device__ int   g_eoff[NPS + 1];

// ---------------- tiny utils ----------------
__global__ void zero_kernel(float* __restrict__ p, int n4) {
    int i = blockIdx.x * blockDim.x + threadIdx.x;
    if (i < n4) ((float4*)p)[i] = make_float4(0.f, 0.f, 0.f, 0.f);
}
__global__ void copy_pad_kernel(const float* __restrict__ x, __nv_bfloat16* __restrict__ xb) {
    int i = blockIdx.x * blockDim.x + threadIdx.x;
    if (i >= NP * 32) return;
    int n = i >> 5;
    float4 v = make_float4(0.f, 0.f, 0.f, 0.f);
    if (n < NN) v = ((const float4*)x)[i];
    *(__nv_bfloat162*)(xb + (size_t)i * 4)     = __floats2bfloat162_rn(v.x, v.y);
    *(__nv_bfloat162*)(xb + (size_t)i * 4 + 2) = __floats2bfloat162_rn(v.z, v.w);
}
__global__ void cvt_bf16_kernel(const float* __restrict__ src,
                                __nv_bfloat16* __restrict__ dst, int n4) {
    int i = blockIdx.x * blockDim.x + threadIdx.x;
    if (i >= n4) return;
    float4 v = ((const float4*)src)[i];
    *(__nv_bfloat162*)(dst + (size_t)i * 4)     = __floats2bfloat162_rn(v.x, v.y);
    *(__nv_bfloat162*)(dst + (size_t)i * 4 + 2) = __floats2bfloat162_rn(v.z, v.w);
}
__global__ void zero2_ints(int* __restrict__ a, int* __restrict__ b, int n) {
    int i = blockIdx.x * blockDim.x + threadIdx.x;
    if (i < n) { a[i] = 0; b[i] = 0; }
}

// ---------------- CSR build ----------------
__global__ void ecount_kernel(const int* __restrict__ dst, const int* __restrict__ attr,
                              int* __restrict__ cnt, int E) {
    int e = blockIdx.x * blockDim.x + threadIdx.x;
    if (e < E) atomicAdd(&cnt[attr[e] * NP + dst[e]], 1);
}
__global__ void scan_kernel(const int* __restrict__ cnt, int* __restrict__ off, int n) {
    __shared__ int ssum[1024];
    int t = threadIdx.x;
    int per = (n + 1023) / 1024;
    int b0 = t * per;
    int b1 = b0 + per; if (b1 > n) b1 = n; if (b0 > n) b0 = n;
    int s = 0;
    for (int i = b0; i < b1; i++) s += cnt[i];
    ssum[t] = s;
    __syncthreads();
    for (int d = 1; d < 1024; d <<= 1) {
        int v = (t >= d) ? ssum[t - d] : 0;
        __syncthreads();
        ssum[t] += v;
        __syncthreads();
    }
    int run = (t == 0) ? 0 : ssum[t - 1];
    if (t == 1023) off[n] = ssum[1023];
    for (int i = b0; i < b1; i++) { off[i] = run; run += cnt[i]; }
}
__global__ void fill_kernel(const int* __restrict__ src, const int* __restrict__ dst,
                            const int* __restrict__ attr, const int* __restrict__ off,
                            int* __restrict__ cur, int* __restrict__ bsrc, int E) {
    int e = blockIdx.x * blockDim.x + threadIdx.x;
    if (e >= E) return;
    int idx = attr[e] * NP + dst[e];
    int pos = off[idx] + atomicAdd(&cur[idx], 1);
    bsrc[pos] = src[e];
}

// ---------------- gather all 3 types ----------------
struct Feat3 { const __nv_bfloat16* p[3]; };

__global__ void gather3_kernel(const int* __restrict__ off, const int* __restrict__ bsrc,
                               Feat3 f, __nv_bfloat16* __restrict__ agg3) {
    int w = (blockIdx.x * blockDim.x + threadIdx.x) >> 5;
    int lane = threadIdx.x & 31;
    if (w >= SS * NP) return;
    int s = w / NP;
    const __nv_bfloat16* feat = f.p[s];
    int e0 = off[w], e1 = off[w + 1];
    float a0 = 0.f, a1 = 0.f, a2 = 0.f, a3 = 0.f;
    for (int e = e0; e < e1; e++) {
        int sn = bsrc[e];
        uint2 u = *(const uint2*)(feat + (size_t)sn * DD + lane * 4);
        __nv_bfloat162 p0 = *(__nv_bfloat162*)&u.x;
        __nv_bfloat162 p1 = *(__nv_bfloat162*)&u.y;
        float2 f0 = __bfloat1622float2(p0), f1 = __bfloat1622float2(p1);
        a0 += f0.x; a1 += f0.y; a2 += f1.x; a3 += f1.y;
    }
    if (e1 > e0) {
        float inv = 1.0f / (float)(e1 - e0);
        a0 *= inv; a1 *= inv; a2 *= inv; a3 *= inv;
    }
    uint2 o;
    *(__nv_bfloat162*)&o.x = __floats2bfloat162_rn(a0, a1);
    *(__nv_bfloat162*)&o.y = __floats2bfloat162_rn(a2, a3);
    *(uint2*)(agg3 + (size_t)w * DD + lane * 4) = o;
}

// ========== weights-stationary streaming GEMM (raw mma.sync, bf16) ==========
// C[M,J] = A[M,128] @ B[J,128]^T + bias.  CTA: 128(M) x 128(N), 16 warps (32x32).
// B fragments register-resident for the CTA's whole M-stream.
#define LDTB 136
#define SMB_B (128 * LDTB * 2)       // 34816
#define SMB_A (128 * LDTB * 2)       // 34816
#define BG_SMEM (SMB_B + 2 * SMB_A)  // 104448
#define GEMM_T 512

struct GemmArgs {
    const __nv_bfloat16* A[6];
    const __nv_bfloat16* B[6];
    const float* bias[6];
    __nv_bfloat16* C[6];
};

__device__ __forceinline__ void cp16(void* s, const void* g) {
    uint32_t sa = (uint32_t)__cvta_generic_to_shared(s);
    asm volatile("cp.async.cg.shared.global [%0], [%1], 16;" :: "r"(sa), "l"(g));
}
__device__ __forceinline__ void ldm_x4(uint32_t* r, const __nv_bfloat16* p) {
    uint32_t sa = (uint32_t)__cvta_generic_to_shared(p);
    asm volatile("ldmatrix.sync.aligned.m8n8.x4.shared.b16 {%0,%1,%2,%3}, [%4];"
                 : "=r"(r[0]), "=r"(r[1]), "=r"(r[2]), "=r"(r[3]) : "r"(sa));
}
__device__ __forceinline__ void ldm_x2(uint32_t* r, const __nv_bfloat16* p) {
    uint32_t sa = (uint32_t)__cvta_generic_to_shared(p);
    asm volatile("ldmatrix.sync.aligned.m8n8.x2.shared.b16 {%0,%1}, [%2];"
                 : "=r"(r[0]), "=r"(r[1]) : "r"(sa));
}
__device__ __forceinline__ void mma16816(float* c, const uint32_t* a, const uint32_t* b) {
    asm volatile(
        "mma.sync.aligned.m16n8k16.row.col.f32.bf16.bf16.f32 "
        "{%0,%1,%2,%3}, {%4,%5,%6,%7}, {%8,%9}, {%0,%1,%2,%3};"
        : "+f"(c[0]), "+f"(c[1]), "+f"(c[2]), "+f"(c[3])
        : "r"(a[0]), "r"(a[1]), "r"(a[2]), "r"(a[3]), "r"(b[0]), "r"(b[1]));
}

__global__ void __launch_bounds__(GEMM_T, 1)
bf16_gemm(GemmArgs ga, int J, int mtiles) {
    int z = blockIdx.z;
    const __nv_bfloat16* A = ga.A[z];
    const __nv_bfloat16* B = ga.B[z];
    const float* bias = ga.bias[z];
    __nv_bfloat16* C = ga.C[z];

    extern __shared__ char smx[];
    __nv_bfloat16* Bs = (__nv_bfloat16*)smx;
    __nv_bfloat16* Abuf0 = (__nv_bfloat16*)(smx + SMB_B);
    __nv_bfloat16* Abuf1 = (__nv_bfloat16*)(smx + SMB_B + SMB_A);

    int tid = threadIdx.x;
    int warp = tid >> 5;
    int lane = tid & 31;
    int mb = (warp >> 2) * 32;      // 4 M bands
    int nb = (warp & 3) * 32;       // 4 N bands
    int bn = blockIdx.x * 128;

    int mt = blockIdx.y;
    if (mt >= mtiles) return;

    // B tile: 128 rows x 128 cols
    for (int slot = tid; slot < 128 * 16; slot += GEMM_T) {
        int r = slot >> 4;
        int c8 = (slot & 15) * 8;
        cp16(Bs + r * LDTB + c8, B + (size_t)(bn + r) * 128 + c8);
    }
    asm volatile("cp.async.commit_group;");
    // first A tile
    for (int slot = tid; slot < 128 * 16; slot += GEMM_T) {
        int r = slot >> 4;
        int c8 = (slot & 15) * 8;
        cp16(Abuf0 + r * LDTB + c8, A + (size_t)mt * 128 * 128 + (size_t)r * 128 + c8);
    }
    asm volatile("cp.async.commit_group;");
    asm volatile("cp.async.wait_group 1;");   // B ready
    __syncthreads();

    // resident B fragments for this warp's 32-col band
    uint32_t bf[4][8][2];
    {
        int lr = lane & 7;
        int ls = (lane >> 3) & 1;
#pragma unroll
        for (int nt = 0; nt < 4; nt++)
#pragma unroll
            for (int kt = 0; kt < 8; kt++)
                ldm_x2(bf[nt][kt], Bs + (nb + nt * 8 + lr) * LDTB + kt * 16 + ls * 8);
    }

    int buf = 0;
    while (mt < mtiles) {
        int nxt = mt + gridDim.y;
        bool pf = (nxt < mtiles);
        __nv_bfloat16* Acur = buf ? Abuf1 : Abuf0;
        __nv_bfloat16* Aalt = buf ? Abuf0 : Abuf1;
        if (pf) {
            for (int slot = tid; slot < 128 * 16; slot += GEMM_T) {
                int r = slot >> 4;
                int c8 = (slot & 15) * 8;
                cp16(Aalt + r * LDTB + c8,
                     A + (size_t)nxt * 128 * 128 + (size_t)r * 128 + c8);
            }
            asm volatile("cp.async.commit_group;");
            asm volatile("cp.async.wait_group 1;");
        } else {
            asm volatile("cp.async.wait_group 0;");
        }
        __syncthreads();

        float acc[2][4][4];
#pragma unroll
        for (int i = 0; i < 2; i++)
#pragma unroll
            for (int nt = 0; nt < 4; nt++)
#pragma unroll
                for (int e = 0; e < 4; e++) acc[i][nt][e] = 0.f;

        int q = lane >> 3;
        int arow = (q & 1) * 8 + (lane & 7);
        int acol = (q >> 1) * 8;
#pragma unroll
        for (int kt = 0; kt < 8; kt++) {
            uint32_t a[2][4];
#pragma unroll
            for (int i = 0; i < 2; i++)
                ldm_x4(a[i], Acur + (mb + i * 16 + arow) * LDTB + kt * 16 + acol);
#pragma unroll
            for (int i = 0; i < 2; i++)
#pragma unroll
                for (int nt = 0; nt < 4; nt++)
                    mma16816(acc[i][nt], a[i], bf[nt][kt]);
        }

        // epilogue: direct bf16 stores with bias
        int bm = mt * 128;
#pragma unroll
        for (int i = 0; i < 2; i++) {
#pragma unroll
            for (int nt = 0; nt < 4; nt++) {
                int r0 = bm + mb + i * 16 + (lane >> 2);
                int cc = bn + nb + nt * 8 + ((lane & 3) << 1);
                float b0v = 0.f, b1v = 0.f;
                if (bias != nullptr) { b0v = bias[cc]; b1v = bias[cc + 1]; }
                *(__nv_bfloat162*)(C + (size_t)r0 * J + cc) =
                    __floats2bfloat162_rn(acc[i][nt][0] + b0v, acc[i][nt][1] + b1v);
                *(__nv_bfloat162*)(C + (size_t)(r0 + 8) * J + cc) =
                    __floats2bfloat162_rn(acc[i][nt][2] + b0v, acc[i][nt][3] + b1v);
            }
        }
        __syncthreads();   // all reads of Acur complete before it becomes prefetch target
        mt = nxt;
        buf ^= 1;
    }
}

// ---------------- GRU math ----------------
__device__ __forceinline__ float tanhapx(float x) {
    float y;
    asm("tanh.approx.f32 %0, %1;" : "=f"(y) : "f"(x));
    return y;
}
__device__ __forceinline__ float sigf(float x) {
    return 0.5f * tanhapx(0.5f * x) + 0.5f;
}
__device__ __forceinline__ float4 ldbf4(const __nv_bfloat16* p) {
    uint2 u = *(const uint2*)p;
    __nv_bfloat162 a = *(__nv_bfloat162*)&u.x;
    __nv_bfloat162 b = *(__nv_bfloat162*)&u.y;
    float2 fa = __bfloat1622float2(a), fb = __bfloat1622float2(b);
    return make_float4(fa.x, fa.y, fb.x, fb.y);
}
__device__ __forceinline__ void stbf4(__nv_bfloat16* p, float4 v) {
    uint2 u;
    *(__nv_bfloat162*)&u.x = __floats2bfloat162_rn(v.x, v.y);
    *(__nv_bfloat162*)&u.y = __floats2bfloat162_rn(v.z, v.w);
    *(uint2*)p = u;
}
__device__ __forceinline__ float4 gru4(float4 ir, float4 iz, float4 in4,
                                       float4 hr, float4 hz, float4 hn, float4 h) {
    float4 o;
    { float r = sigf(ir.x + hr.x), z = sigf(iz.x + hz.x);
      float nn = tanhapx(in4.x + r * hn.x); o.x = (1.f - z) * nn + z * h.x; }
    { float r = sigf(ir.y + hr.y), z = sigf(iz.y + hz.y);
      float nn = tanhapx(in4.y + r * hn.y); o.y = (1.f - z) * nn + z * h.y; }
    { float r = sigf(ir.z + hr.z), z = sigf(iz.z + hz.z);
      float nn = tanhapx(in4.z + r * hn.z); o.z = (1.f - z) * nn + z * h.z; }
    { float r = sigf(ir.w + hr.w), z = sigf(iz.w + hz.w);
      float nn = tanhapx(in4.w + r * hn.w); o.w = (1.f - z) * nn + z * h.w; }
    return o;
}

__global__ void gru3_first_kernel(const __nv_bfloat16* __restrict__ gi3,
                                  const __nv_bfloat16* __restrict__ gh3,
                                  const __nv_bfloat16* __restrict__ xb,
                                  __nv_bfloat16* __restrict__ hb3) {
    int idx = blockIdx.x * blockDim.x + threadIdx.x;
    if (idx >= NN * 32) return;
    int s = blockIdx.y;
    int n = idx >> 5;
    int c = (idx & 31) * 4;
    const __nv_bfloat16* gir = gi3 + (size_t)s * NP * 384 + (size_t)n * 384;
    const __nv_bfloat16* ghr = gh3 + (size_t)s * NP * 384 + (size_t)n * 384;
    float4 h = ldbf4(xb + (size_t)n * 128 + c);
    float4 o = gru4(ldbf4(gir + c), ldbf4(gir + 128 + c), ldbf4(gir + 256 + c),
                    ldbf4(ghr + c), ldbf4(ghr + 128 + c), ldbf4(ghr + 256 + c), h);
    stbf4(hb3 + (size_t)s * NP * 128 + (size_t)n * 128 + c, o);
}

__global__ void gru3_final_kernel(const __nv_bfloat16* __restrict__ gi3,
                                  const __nv_bfloat16* __restrict__ gh3,
                                  const __nv_bfloat16* __restrict__ hb3,
                                  __nv_bfloat16* __restrict__ xb) {
    int idx = blockIdx.x * blockDim.x + threadIdx.x;
    if (idx >= NN * 32) return;
    int n = idx >> 5;
    int c = (idx & 31) * 4;
    float4 xv = make_float4(0.f, 0.f, 0.f, 0.f);
#pragma unroll
    for (int s = 0; s < SS; s++) {
        const __nv_bfloat16* gir = gi3 + (size_t)s * NP * 384 + (size_t)n * 384;
        const __nv_bfloat16* ghr = gh3 + (size_t)s * NP * 384 + (size_t)n * 384;
        float4 h = ldbf4(hb3 + (size_t)s * NP * 128 + (size_t)n * 128 + c);
        float4 o = gru4(ldbf4(gir + c), ldbf4(gir + 128 + c), ldbf4(gir + 256 + c),
                        ldbf4(ghr + c), ldbf4(ghr + 128 + c), ldbf4(ghr + 256 + c), h);
        xv.x += o.x; xv.y += o.y; xv.z += o.z; xv.w += o.w;
    }
    xv.x *= (1.0f / 3.0f); xv.y *= (1.0f / 3.0f);
    xv.z *= (1.0f / 3.0f); xv.w *= (1.0f / 3.0f);
    stbf4(xb + (size_t)n * 128 + c, xv);
}

// ---------------- pooling / MLP ----------------
__global__ void cnt_kernel(const int* __restrict__ batch, float* __restrict__ cnt, int n) {
    int i = blockIdx.x * blockDim.x + threadIdx.x;
    if (i < n) atomicAdd(&cnt[batch[i]], 1.0f);
}
__global__ void pool_kernel(const __nv_bfloat16* __restrict__ xb, const int* __restrict__ batch,
                            float* __restrict__ pool) {
    int idx = blockIdx.x * blockDim.x + threadIdx.x;
    if (idx >= NN * 32) return;
    int n = idx >> 5;
    int c = (idx & 31) * 4;
    int g = batch[n];
    float4 v = ldbf4(xb + (size_t)n * 128 + c);
    float* o = pool + (size_t)g * 128 + c;
    asm volatile("red.global.add.v4.f32 [%0], {%1,%2,%3,%4};"
                 :: "l"(o), "f"(v.x), "f"(v.y), "f"(v.z), "f"(v.w) : "memory");
}
__global__ void mlp_kernel(const float* __restrict__ pool, const float* __restrict__ cnt,
                           const float* __restrict__ pt,
                           const float* __restrict__ fc1w, const float* __restrict__ fc1b,
                           const float* __restrict__ fc2w, const float* __restrict__ fc2b,
                           const float* __restrict__ fclw, const float* __restrict__ fclb,
                           float* __restrict__ out) {
    __shared__ float h1[GG * 80];
    __shared__ float h2[GG * 80];
    int tid = threadIdx.x;
    for (int t = tid; t < GG * 80; t += blockDim.x) {
        int g = t / 80, j = t - (t / 80) * 80;
        float ic = 1.0f / fmaxf(cnt[g], 1.0f);
        float acc = fc1b[j];
        const float* w = fc1w + j * 129;
        const float* p = pool + g * 128;
        for (int k = 0; k < 128; k++) acc = fmaf(p[k] * ic, w[k], acc);
        acc = fmaf(pt[g], w[128], acc);
        h1[t] = acc > 0.f ? acc : 0.01f * acc;
    }
    __syncthreads();
    for (int t = tid; t < GG * 80; t += blockDim.x) {
        int g = t / 80, j = t - (t / 80) * 80;
        float acc = fc2b[j];
        const float* w = fc2w + j * 80;
        const float* hh = h1 + g * 80;
        for (int k = 0; k < 80; k++) acc = fmaf(hh[k], w[k], acc);
        h2[t] = acc > 0.f ? acc : 0.01f * acc;
    }
    __syncthreads();
    for (int t = tid; t < GG * OUTD; t += blockDim.x) {
        int g = t / OUTD, o = t - (t / OUTD) * OUTD;
        float acc = fclb[o];
        const float* w = fclw + o * 80;
        const float* hh = h2 + g * 80;
        for (int k = 0; k < 80; k++) acc = fmaf(hh[k], w[k], acc);
        out[t] = acc;
    }
}

// ---------------- host launcher ----------------
extern "C" void kernel_launch(void* const* d_in, const int* in_sizes, int n_in,
                              void* d_out, int out_size) {
    (void)in_sizes; (void)n_in; (void)out_size;
    const float* x     = (const float*)d_in[0];
    const int*   eidx  = (const int*)d_in[1];
    const int*   eattr = (const int*)d_in[2];
    const int*   batch = (const int*)d_in[3];
    const float* pt    = (const float*)d_in[4];
    const float* W     = (const float*)d_in[5];
    const float* wih   = (const float*)d_in[6];
    const float* whh   = (const float*)d_in[7];
    const float* bih   = (const float*)d_in[8];
    const float* bhh   = (const float*)d_in[9];
    const float* fc1w  = (const float*)d_in[10];
    const float* fc1b  = (const float*)d_in[11];
    const float* fc2w  = (const float*)d_in[12];
    const float* fc2b  = (const float*)d_in[13];
    const float* fclw  = (const float*)d_in[14];
    const float* fclb  = (const float*)d_in[15];
    float* out = (float*)d_out;

    const int* src = eidx;
    const int* dst = eidx + EE;

    float *poolp, *cntp;
    __nv_bfloat16 *xb, *hb3, *agg3, *gi3, *gh3, *wcb, *wihb, *whhb, *Wb;
    int *bsrcp, *ecntp, *ecurp, *eoffp;
    cudaGetSymbolAddress((void**)&xb,    g_xb);
    cudaGetSymbolAddress((void**)&hb3,   g_hb3);
    cudaGetSymbolAddress((void**)&agg3,  g_agg3);
    cudaGetSymbolAddress((void**)&gi3,   g_gi3);
    cudaGetSymbolAddress((void**)&gh3,   g_gh3);
    cudaGetSymbolAddress((void**)&wcb,   g_wcb);
    cudaGetSymbolAddress((void**)&wihb,  g_wihb);
    cudaGetSymbolAddress((void**)&whhb,  g_whhb);
    cudaGetSymbolAddress((void**)&Wb,    g_Wb);
    cudaGetSymbolAddress((void**)&poolp, g_pool);
    cudaGetSymbolAddress((void**)&cntp,  g_cnt);
    cudaGetSymbolAddress((void**)&bsrcp, g_bsrc);
    cudaGetSymbolAddress((void**)&ecntp, g_ecnt);
    cudaGetSymbolAddress((void**)&ecurp, g_ecur);
    cudaGetSymbolAddress((void**)&eoffp, g_eoff);

    cudaFuncSetAttribute(bf16_gemm, cudaFuncAttributeMaxDynamicSharedMemorySize, BG_SMEM);

    const int TB = 256;
    dim3 g3(3, 16, 3);   // 144 CTAs (1 per SM, 512 thr); ~49 M-tiles per CTA

    // ---- prologue ----
    copy_pad_kernel<<<(NP * 32 + TB - 1) / TB, TB>>>(x, xb);                    // 0
    cvt_bf16_kernel<<<(SS * 384 * 32 + TB - 1) / TB, TB>>>(whh, whhb,
                                                           SS * 384 * 32);      // 1
    zero2_ints<<<(NPS + TB - 1) / TB, TB>>>(ecntp, ecurp, NPS);                 // 2
    // 3 (PROFILED): gh GEMM for superstep (0,0)
    {
        GemmArgs ga;
        for (int s = 0; s < 3; s++) {
            ga.A[s] = xb;
            ga.B[s] = whhb + (size_t)s * 384 * 128;
            ga.bias[s] = bhh + s * 384;
            ga.C[s] = gh3 + (size_t)s * NP * 384;
        }
        bf16_gemm<<<g3, GEMM_T, BG_SMEM>>>(ga, 384, M_TILES);
    }
    cvt_bf16_kernel<<<(SS * 384 * 32 + TB - 1) / TB, TB>>>(wih, wihb, SS * 384 * 32);
    cvt_bf16_kernel<<<(SS * 2 * 128 * 32 + TB - 1) / TB, TB>>>(W, Wb, SS * 2 * 128 * 32);
    ecount_kernel<<<(EE + TB - 1) / TB, TB>>>(dst, eattr, ecntp, EE);
    scan_kernel<<<1, 1024>>>(ecntp, eoffp, NPS);
    fill_kernel<<<(EE + TB - 1) / TB, TB>>>(src, dst, eattr, eoffp, ecurp, bsrcp, EE);
    // combined weights Wc[s,i] = wih[s] @ W[s,i]^T
    {
        GemmArgs ga;
        for (int z = 0; z < 6; z++) {
            int s = z / 2, i = z % 2;
            ga.A[z] = wihb + (size_t)s * 384 * 128;
            ga.B[z] = Wb + (size_t)(s * 2 + i) * 128 * 128;
            ga.bias[z] = nullptr;
            ga.C[z] = wcb + (size_t)(s * 2 + i) * 384 * 128;
        }
        bf16_gemm<<<dim3(1, 3, 6), GEMM_T, BG_SMEM>>>(ga, 128, 3);
    }

    // ---- main loop: 4 supersteps ----
    int step = 0;
    for (int pass = 0; pass < 2; pass++) {
        for (int i = 0; i < 2; i++, step++) {
            Feat3 f;
            if (i == 0) { f.p[0] = xb; f.p[1] = xb; f.p[2] = xb; }
            else {
                f.p[0] = hb3;
                f.p[1] = hb3 + (size_t)NP * 128;
                f.p[2] = hb3 + (size_t)2 * NP * 128;
            }
            gather3_kernel<<<(SS * NP * 32 + TB - 1) / TB, TB>>>(eoffp, bsrcp, f, agg3);
            if (step > 0) {
                GemmArgs ga;
                for (int s = 0; s < 3; s++) {
                    ga.A[s] = (i == 0) ? xb : (hb3 + (size_t)s * NP * 128);
                    ga.B[s] = whhb + (size_t)s * 384 * 128;
                    ga.bias[s] = bhh + s * 384;
                    ga.C[s] = gh3 + (size_t)s * NP * 384;
                }
                bf16_gemm<<<g3, GEMM_T, BG_SMEM>>>(ga, 384, M_TILES);
            }
            {
                GemmArgs ga;
                for (int s = 0; s < 3; s++) {
                    ga.A[s] = agg3 + (size_t)s * NP * 128;
                    ga.B[s] = wcb + (size_t)(s * 2 + i) * 384 * 128;
                    ga.bias[s] = bih + s * 384;
                    ga.C[s] = gi3 + (size_t)s * NP * 384;
                }
                bf16_gemm<<<g3, GEMM_T, BG_SMEM>>>(ga, 384, M_TILES);
            }
            if (i == 0)
                gru3_first_kernel<<<dim3((NN * 32 + TB - 1) / TB, 3), TB>>>(
                    gi3, gh3, xb, hb3);
            else
                gru3_final_kernel<<<(NN * 32 + TB - 1) / TB, TB>>>(gi3, gh3, hb3, xb);
        }
    }

    // ---- pooling + MLP ----
    zero_kernel<<<(GG * DD / 4 + TB - 1) / TB, TB>>>(poolp, GG * DD / 4);
    zero_kernel<<<1, GG / 4>>>(cntp, GG / 4);
    cnt_kernel<<<(NN + TB - 1) / TB, TB>>>(batch, cntp, NN);
    pool_kernel<<<(NN * 32 + TB - 1) / TB, TB>>>(xb, batch, poolp);
    mlp_kernel<<<1, 256>>>(poolp, cntp, pt, fc1w, fc1b, fc2w, fc2b, fclw, fclb, out);
}

// round 13
// speedup vs baseline: 1.3912x; 1.1291x over previous
#include <cuda_runtime.h>
#include <cuda_bf16.h>
#include <math.h>
#include <stdint.h>

#define NN 100000
#define NP 100096
#define EE 600000
#define DD 128
#define SS 3
#define GG 64
#define OUTD 2
#define NPS (SS * NP)
#define M_TILES (NP / 128)        // 782

// ---------------- device scratch ----------------
__device__ __nv_bfloat16 g_xb[NP * DD];
__device__ __nv_bfloat16 g_hb3[SS * NP * DD];
__device__ __nv_bfloat16 g_agg3[SS * NP * DD];
__device__ __nv_bfloat16 g_gi3[SS * NP * 3 * DD];
__device__ __nv_bfloat16 g_gh3[SS * NP * 3 * DD];
__device__ __nv_bfloat16 g_wcb[SS * 2 * 3 * DD * DD];
__device__ __nv_bfloat16 g_wihb[SS * 3 * DD * DD];
__device__ __nv_bfloat16 g_whhb[SS * 3 * DD * DD];
__device__ __nv_bfloat16 g_Wb[SS * 2 * DD * DD];
__device__ float g_pool[GG * DD];
__device__ float g_cnt[GG];
__device__ int   g_bsrc[EE];
__device__ int   g_ecnt[NPS];
__device__ int   g_ecur[NPS];
__device__ int   g_eoff[NPS + 1];

// ---------------- tiny utils ----------------
__global__ void zero_kernel(float* __restrict__ p, int n4) {
    int i = blockIdx.x * blockDim.x + threadIdx.x;
    if (i < n4) ((float4*)p)[i] = make_float4(0.f, 0.f, 0.f, 0.f);
}
__global__ void copy_pad_kernel(const float* __restrict__ x, __nv_bfloat16* __restrict__ xb) {
    int i = blockIdx.x * blockDim.x + threadIdx.x;
    if (i >= NP * 32) return;
    int n = i >> 5;
    float4 v = make_float4(0.f, 0.f, 0.f, 0.f);
    if (n < NN) v = ((const float4*)x)[i];
    *(__nv_bfloat162*)(xb + (size_t)i * 4)     = __floats2bfloat162_rn(v.x, v.y);
    *(__nv_bfloat162*)(xb + (size_t)i * 4 + 2) = __floats2bfloat162_rn(v.z, v.w);
}
__global__ void cvt_bf16_kernel(const float* __restrict__ src,
                                __nv_bfloat16* __restrict__ dst, int n4) {
    int i = blockIdx.x * blockDim.x + threadIdx.x;
    if (i >= n4) return;
    float4 v = ((const float4*)src)[i];
    *(__nv_bfloat162*)(dst + (size_t)i * 4)     = __floats2bfloat162_rn(v.x, v.y);
    *(__nv_bfloat162*)(dst + (size_t)i * 4 + 2) = __floats2bfloat162_rn(v.z, v.w);
}
__global__ void zero2_ints(int* __restrict__ a, int* __restrict__ b, int n) {
    int i = blockIdx.x * blockDim.x + threadIdx.x;
    if (i < n) { a[i] = 0; b[i] = 0; }
}

// ---------------- CSR build ----------------
__global__ void ecount_kernel(const int* __restrict__ dst, const int* __restrict__ attr,
                              int* __restrict__ cnt, int E) {
    int e = blockIdx.x * blockDim.x + threadIdx.x;
    if (e < E) atomicAdd(&cnt[attr[e] * NP + dst[e]], 1);
}
__global__ void scan_kernel(const int* __restrict__ cnt, int* __restrict__ off, int n) {
    __shared__ int ssum[1024];
    int t = threadIdx.x;
    int per = (n + 1023) / 1024;
    int b0 = t * per;
    int b1 = b0 + per; if (b1 > n) b1 = n; if (b0 > n) b0 = n;
    int s = 0;
    for (int i = b0; i < b1; i++) s += cnt[i];
    ssum[t] = s;
    __syncthreads();
    for (int d = 1; d < 1024; d <<= 1) {
        int v = (t >= d) ? ssum[t - d] : 0;
        __syncthreads();
        ssum[t] += v;
        __syncthreads();
    }
    int run = (t == 0) ? 0 : ssum[t - 1];
    if (t == 1023) off[n] = ssum[1023];
    for (int i = b0; i < b1; i++) { off[i] = run; run += cnt[i]; }
}
__global__ void fill_kernel(const int* __restrict__ src, const int* __restrict__ dst,
                            const int* __restrict__ attr, const int* __restrict__ off,
                            int* __restrict__ cur, int* __restrict__ bsrc, int E) {
    int e = blockIdx.x * blockDim.x + threadIdx.x;
    if (e >= E) return;
    int idx = attr[e] * NP + dst[e];
    int pos = off[idx] + atomicAdd(&cur[idx], 1);
    bsrc[pos] = src[e];
}

// ---------------- gather all 3 types ----------------
struct Feat3 { const __nv_bfloat16* p[3]; };

__global__ void gather3_kernel(const int* __restrict__ off, const int* __restrict__ bsrc,
                               Feat3 f, __nv_bfloat16* __restrict__ agg3) {
    int w = (blockIdx.x * blockDim.x + threadIdx.x) >> 5;
    int lane = threadIdx.x & 31;
    if (w >= SS * NP) return;
    int s = w / NP;
    const __nv_bfloat16* feat = f.p[s];
    int e0 = off[w], e1 = off[w + 1];
    float a0 = 0.f, a1 = 0.f, a2 = 0.f, a3 = 0.f;
    for (int e = e0; e < e1; e++) {
        int sn = bsrc[e];
        uint2 u = *(const uint2*)(feat + (size_t)sn * DD + lane * 4);
        __nv_bfloat162 p0 = *(__nv_bfloat162*)&u.x;
        __nv_bfloat162 p1 = *(__nv_bfloat162*)&u.y;
        float2 f0 = __bfloat1622float2(p0), f1 = __bfloat1622float2(p1);
        a0 += f0.x; a1 += f0.y; a2 += f1.x; a3 += f1.y;
    }
    if (e1 > e0) {
        float inv = 1.0f / (float)(e1 - e0);
        a0 *= inv; a1 *= inv; a2 *= inv; a3 *= inv;
    }
    uint2 o;
    *(__nv_bfloat162*)&o.x = __floats2bfloat162_rn(a0, a1);
    *(__nv_bfloat162*)&o.y = __floats2bfloat162_rn(a2, a3);
    *(uint2*)(agg3 + (size_t)w * DD + lane * 4) = o;
}

// ========== weights-stationary streaming GEMM (raw mma.sync, bf16) ==========
#define LDTB 136
#define SMB_B (128 * LDTB * 2)
#define SMB_A (128 * LDTB * 2)
#define BG_SMEM (SMB_B + 2 * SMB_A)  // 104448
#define GEMM_T 512

struct GemmArgs {
    const __nv_bfloat16* A[6];
    const __nv_bfloat16* B[6];
    const float* bias[6];
    __nv_bfloat16* C[6];
};

__device__ __forceinline__ void cp16(void* s, const void* g) {
    uint32_t sa = (uint32_t)__cvta_generic_to_shared(s);
    asm volatile("cp.async.cg.shared.global [%0], [%1], 16;" :: "r"(sa), "l"(g));
}
__device__ __forceinline__ void ldm_x4(uint32_t* r, const __nv_bfloat16* p) {
    uint32_t sa = (uint32_t)__cvta_generic_to_shared(p);
    asm volatile("ldmatrix.sync.aligned.m8n8.x4.shared.b16 {%0,%1,%2,%3}, [%4];"
                 : "=r"(r[0]), "=r"(r[1]), "=r"(r[2]), "=r"(r[3]) : "r"(sa));
}
__device__ __forceinline__ void ldm_x2(uint32_t* r, const __nv_bfloat16* p) {
    uint32_t sa = (uint32_t)__cvta_generic_to_shared(p);
    asm volatile("ldmatrix.sync.aligned.m8n8.x2.shared.b16 {%0,%1}, [%2];"
                 : "=r"(r[0]), "=r"(r[1]) : "r"(sa));
}
__device__ __forceinline__ void mma16816(float* c, const uint32_t* a, const uint32_t* b) {
    asm volatile(
        "mma.sync.aligned.m16n8k16.row.col.f32.bf16.bf16.f32 "
        "{%0,%1,%2,%3}, {%4,%5,%6,%7}, {%8,%9}, {%0,%1,%2,%3};"
        : "+f"(c[0]), "+f"(c[1]), "+f"(c[2]), "+f"(c[3])
        : "r"(a[0]), "r"(a[1]), "r"(a[2]), "r"(a[3]), "r"(b[0]), "r"(b[1]));
}

__global__ void __launch_bounds__(GEMM_T, 1)
bf16_gemm(GemmArgs ga, int J, int mtiles) {
    int z = blockIdx.z;
    const __nv_bfloat16* A = ga.A[z];
    const __nv_bfloat16* B = ga.B[z];
    const float* bias = ga.bias[z];
    __nv_bfloat16* C = ga.C[z];

    extern __shared__ char smx[];
    __nv_bfloat16* Bs = (__nv_bfloat16*)smx;
    __nv_bfloat16* Abuf0 = (__nv_bfloat16*)(smx + SMB_B);
    __nv_bfloat16* Abuf1 = (__nv_bfloat16*)(smx + SMB_B + SMB_A);

    int tid = threadIdx.x;
    int warp = tid >> 5;
    int lane = tid & 31;
    int mb = (warp >> 2) * 32;
    int nb = (warp & 3) * 32;
    int bn = blockIdx.x * 128;

    int mt = blockIdx.y;
    if (mt >= mtiles) return;

    for (int slot = tid; slot < 128 * 16; slot += GEMM_T) {
        int r = slot >> 4;
        int c8 = (slot & 15) * 8;
        cp16(Bs + r * LDTB + c8, B + (size_t)(bn + r) * 128 + c8);
    }
    asm volatile("cp.async.commit_group;");
    for (int slot = tid; slot < 128 * 16; slot += GEMM_T) {
        int r = slot >> 4;
        int c8 = (slot & 15) * 8;
        cp16(Abuf0 + r * LDTB + c8, A + (size_t)mt * 128 * 128 + (size_t)r * 128 + c8);
    }
    asm volatile("cp.async.commit_group;");
    asm volatile("cp.async.wait_group 1;");
    __syncthreads();

    uint32_t bf[4][8][2];
    {
        int lr = lane & 7;
        int ls = (lane >> 3) & 1;
#pragma unroll
        for (int nt = 0; nt < 4; nt++)
#pragma unroll
            for (int kt = 0; kt < 8; kt++)
                ldm_x2(bf[nt][kt], Bs + (nb + nt * 8 + lr) * LDTB + kt * 16 + ls * 8);
    }

    int buf = 0;
    while (mt < mtiles) {
        int nxt = mt + gridDim.y;
        bool pf = (nxt < mtiles);
        __nv_bfloat16* Acur = buf ? Abuf1 : Abuf0;
        __nv_bfloat16* Aalt = buf ? Abuf0 : Abuf1;
        if (pf) {
            for (int slot = tid; slot < 128 * 16; slot += GEMM_T) {
                int r = slot >> 4;
                int c8 = (slot & 15) * 8;
                cp16(Aalt + r * LDTB + c8,
                     A + (size_t)nxt * 128 * 128 + (size_t)r * 128 + c8);
            }
            asm volatile("cp.async.commit_group;");
            asm volatile("cp.async.wait_group 1;");
        } else {
            asm volatile("cp.async.wait_group 0;");
        }
        __syncthreads();

        float acc[2][4][4];
#pragma unroll
        for (int i = 0; i < 2; i++)
#pragma unroll
            for (int nt = 0; nt < 4; nt++)
#pragma unroll
                for (int e = 0; e < 4; e++) acc[i][nt][e] = 0.f;

        int q = lane >> 3;
        int arow = (q & 1) * 8 + (lane & 7);
        int acol = (q >> 1) * 8;
#pragma unroll
        for (int kt = 0; kt < 8; kt++) {
            uint32_t a[2][4];
#pragma unroll
            for (int i = 0; i < 2; i++)
                ldm_x4(a[i], Acur + (mb + i * 16 + arow) * LDTB + kt * 16 + acol);
#pragma unroll
            for (int i = 0; i < 2; i++)
#pragma unroll
                for (int nt = 0; nt < 4; nt++)
                    mma16816(acc[i][nt], a[i], bf[nt][kt]);
        }

        int bm = mt * 128;
#pragma unroll
        for (int i = 0; i < 2; i++) {
#pragma unroll
            for (int nt = 0; nt < 4; nt++) {
                int r0 = bm + mb + i * 16 + (lane >> 2);
                int cc = bn + nb + nt * 8 + ((lane & 3) << 1);
                float b0v = 0.f, b1v = 0.f;
                if (bias != nullptr) { b0v = bias[cc]; b1v = bias[cc + 1]; }
                *(__nv_bfloat162*)(C + (size_t)r0 * J + cc) =
                    __floats2bfloat162_rn(acc[i][nt][0] + b0v, acc[i][nt][1] + b1v);
                *(__nv_bfloat162*)(C + (size_t)(r0 + 8) * J + cc) =
                    __floats2bfloat162_rn(acc[i][nt][2] + b0v, acc[i][nt][3] + b1v);
            }
        }
        __syncthreads();
        mt = nxt;
        buf ^= 1;
    }
}

// ---------------- GRU math ----------------
__device__ __forceinline__ float tanhapx(float x) {
    float y;
    asm("tanh.approx.f32 %0, %1;" : "=f"(y) : "f"(x));
    return y;
}
__device__ __forceinline__ float sigf(float x) {
    return 0.5f * tanhapx(0.5f * x) + 0.5f;
}
__device__ __forceinline__ float4 ldbf4(const __nv_bfloat16* p) {
    uint2 u = *(const uint2*)p;
    __nv_bfloat162 a = *(__nv_bfloat162*)&u.x;
    __nv_bfloat162 b = *(__nv_bfloat162*)&u.y;
    float2 fa = __bfloat1622float2(a), fb = __bfloat1622float2(b);
    return make_float4(fa.x, fa.y, fb.x, fb.y);
}
__device__ __forceinline__ void stbf4(__nv_bfloat16* p, float4 v) {
    uint2 u;
    *(__nv_bfloat162*)&u.x = __floats2bfloat162_rn(v.x, v.y);
    *(__nv_bfloat162*)&u.y = __floats2bfloat162_rn(v.z, v.w);
    *(uint2*)p = u;
}
__device__ __forceinline__ float4 gru4(float4 ir, float4 iz, float4 in4,
                                       float4 hr, float4 hz, float4 hn, float4 h) {
    float4 o;
    { float r = sigf(ir.x + hr.x), z = sigf(iz.x + hz.x);
      float nn = tanhapx(in4.x + r * hn.x); o.x = (1.f - z) * nn + z * h.x; }
    { float r = sigf(ir.y + hr.y), z = sigf(iz.y + hz.y);
      float nn = tanhapx(in4.y + r * hn.y); o.y = (1.f - z) * nn + z * h.y; }
    { float r = sigf(ir.z + hr.z), z = sigf(iz.z + hz.z);
      float nn = tanhapx(in4.z + r * hn.z); o.z = (1.f - z) * nn + z * h.z; }
    { float r = sigf(ir.w + hr.w), z = sigf(iz.w + hz.w);
      float nn = tanhapx(in4.w + r * hn.w); o.w = (1.f - z) * nn + z * h.w; }
    return o;
}

__global__ void gru3_first_kernel(const __nv_bfloat16* __restrict__ gi3,
                                  const __nv_bfloat16* __restrict__ gh3,
                                  const __nv_bfloat16* __restrict__ xb,
                                  __nv_bfloat16* __restrict__ hb3) {
    int idx = blockIdx.x * blockDim.x + threadIdx.x;
    if (idx >= NN * 32) return;
    int s = blockIdx.y;
    int n = idx >> 5;
    int c = (idx & 31) * 4;
    const __nv_bfloat16* gir = gi3 + (size_t)s * NP * 384 + (size_t)n * 384;
    const __nv_bfloat16* ghr = gh3 + (size_t)s * NP * 384 + (size_t)n * 384;
    float4 h = ldbf4(xb + (size_t)n * 128 + c);
    float4 o = gru4(ldbf4(gir + c), ldbf4(gir + 128 + c), ldbf4(gir + 256 + c),
                    ldbf4(ghr + c), ldbf4(ghr + 128 + c), ldbf4(ghr + 256 + c), h);
    stbf4(hb3 + (size_t)s * NP * 128 + (size_t)n * 128 + c, o);
}

__global__ void gru3_final_kernel(const __nv_bfloat16* __restrict__ gi3,
                                  const __nv_bfloat16* __restrict__ gh3,
                                  const __nv_bfloat16* __restrict__ hb3,
                                  __nv_bfloat16* __restrict__ xb) {
    int idx = blockIdx.x * blockDim.x + threadIdx.x;
    if (idx >= NN * 32) return;
    int n = idx >> 5;
    int c = (idx & 31) * 4;
    float4 xv = make_float4(0.f, 0.f, 0.f, 0.f);
#pragma unroll
    for (int s = 0; s < SS; s++) {
        const __nv_bfloat16* gir = gi3 + (size_t)s * NP * 384 + (size_t)n * 384;
        const __nv_bfloat16* ghr = gh3 + (size_t)s * NP * 384 + (size_t)n * 384;
        float4 h = ldbf4(hb3 + (size_t)s * NP * 128 + (size_t)n * 128 + c);
        float4 o = gru4(ldbf4(gir + c), ldbf4(gir + 128 + c), ldbf4(gir + 256 + c),
                        ldbf4(ghr + c), ldbf4(ghr + 128 + c), ldbf4(ghr + 256 + c), h);
        xv.x += o.x; xv.y += o.y; xv.z += o.z; xv.w += o.w;
    }
    xv.x *= (1.0f / 3.0f); xv.y *= (1.0f / 3.0f);
    xv.z *= (1.0f / 3.0f); xv.w *= (1.0f / 3.0f);
    stbf4(xb + (size_t)n * 128 + c, xv);
}

// ---------------- pooling / MLP ----------------
__global__ void cnt_kernel(const int* __restrict__ batch, float* __restrict__ cnt, int n) {
    int i = blockIdx.x * blockDim.x + threadIdx.x;
    if (i < n) atomicAdd(&cnt[batch[i]], 1.0f);
}
__global__ void pool_kernel(const __nv_bfloat16* __restrict__ xb, const int* __restrict__ batch,
                            float* __restrict__ pool) {
    int idx = blockIdx.x * blockDim.x + threadIdx.x;
    if (idx >= NN * 32) return;
    int n = idx >> 5;
    int c = (idx & 31) * 4;
    int g = batch[n];
    float4 v = ldbf4(xb + (size_t)n * 128 + c);
    float* o = pool + (size_t)g * 128 + c;
    asm volatile("red.global.add.v4.f32 [%0], {%1,%2,%3,%4};"
                 :: "l"(o), "f"(v.x), "f"(v.y), "f"(v.z), "f"(v.w) : "memory");
}
__global__ void mlp_kernel(const float* __restrict__ pool, const float* __restrict__ cnt,
                           const float* __restrict__ pt,
                           const float* __restrict__ fc1w, const float* __restrict__ fc1b,
                           const float* __restrict__ fc2w, const float* __restrict__ fc2b,
                           const float* __restrict__ fclw, const float* __restrict__ fclb,
                           float* __restrict__ out) {
    __shared__ float h1[GG * 80];
    __shared__ float h2[GG * 80];
    int tid = threadIdx.x;
    for (int t = tid; t < GG * 80; t += blockDim.x) {
        int g = t / 80, j = t - (t / 80) * 80;
        float ic = 1.0f / fmaxf(cnt[g], 1.0f);
        float acc = fc1b[j];
        const float* w = fc1w + j * 129;
        const float* p = pool + g * 128;
        for (int k = 0; k < 128; k++) acc = fmaf(p[k] * ic, w[k], acc);
        acc = fmaf(pt[g], w[128], acc);
        h1[t] = acc > 0.f ? acc : 0.01f * acc;
    }
    __syncthreads();
    for (int t = tid; t < GG * 80; t += blockDim.x) {
        int g = t / 80, j = t - (t / 80) * 80;
        float acc = fc2b[j];
        const float* w = fc2w + j * 80;
        const float* hh = h1 + g * 80;
        for (int k = 0; k < 80; k++) acc = fmaf(hh[k], w[k], acc);
        h2[t] = acc > 0.f ? acc : 0.01f * acc;
    }
    __syncthreads();
    for (int t = tid; t < GG * OUTD; t += blockDim.x) {
        int g = t / OUTD, o = t - (t / OUTD) * OUTD;
        float acc = fclb[o];
        const float* w = fclw + o * 80;
        const float* hh = h2 + g * 80;
        for (int k = 0; k < 80; k++) acc = fmaf(hh[k], w[k], acc);
        out[t] = acc;
    }
}

// ---------------- host launcher ----------------
extern "C" void kernel_launch(void* const* d_in, const int* in_sizes, int n_in,
                              void* d_out, int out_size) {
    (void)in_sizes; (void)n_in; (void)out_size;
    const float* x     = (const float*)d_in[0];
    const int*   eidx  = (const int*)d_in[1];
    const int*   eattr = (const int*)d_in[2];
    const int*   batch = (const int*)d_in[3];
    const float* pt    = (const float*)d_in[4];
    const float* W     = (const float*)d_in[5];
    const float* wih   = (const float*)d_in[6];
    const float* whh   = (const float*)d_in[7];
    const float* bih   = (const float*)d_in[8];
    const float* bhh   = (const float*)d_in[9];
    const float* fc1w  = (const float*)d_in[10];
    const float* fc1b  = (const float*)d_in[11];
    const float* fc2w  = (const float*)d_in[12];
    const float* fc2b  = (const float*)d_in[13];
    const float* fclw  = (const float*)d_in[14];
    const float* fclb  = (const float*)d_in[15];
    float* out = (float*)d_out;

    const int* src = eidx;
    const int* dst = eidx + EE;

    float *poolp, *cntp;
    __nv_bfloat16 *xb, *hb3, *agg3, *gi3, *gh3, *wcb, *wihb, *whhb, *Wb;
    int *bsrcp, *ecntp, *ecurp, *eoffp;
    cudaGetSymbolAddress((void**)&xb,    g_xb);
    cudaGetSymbolAddress((void**)&hb3,   g_hb3);
    cudaGetSymbolAddress((void**)&agg3,  g_agg3);
    cudaGetSymbolAddress((void**)&gi3,   g_gi3);
    cudaGetSymbolAddress((void**)&gh3,   g_gh3);
    cudaGetSymbolAddress((void**)&wcb,   g_wcb);
    cudaGetSymbolAddress((void**)&wihb,  g_wihb);
    cudaGetSymbolAddress((void**)&whhb,  g_whhb);
    cudaGetSymbolAddress((void**)&Wb,    g_Wb);
    cudaGetSymbolAddress((void**)&poolp, g_pool);
    cudaGetSymbolAddress((void**)&cntp,  g_cnt);
    cudaGetSymbolAddress((void**)&bsrcp, g_bsrc);
    cudaGetSymbolAddress((void**)&ecntp, g_ecnt);
    cudaGetSymbolAddress((void**)&ecurp, g_ecur);
    cudaGetSymbolAddress((void**)&eoffp, g_eoff);

    cudaFuncSetAttribute(bf16_gemm, cudaFuncAttributeMaxDynamicSharedMemorySize, BG_SMEM);

    const int TB = 256;
    dim3 g3(3, 16, 3);

    // side stream + events (same pattern as R10 — passed graph capture)
    cudaStream_t s2;
    cudaStreamCreateWithFlags(&s2, cudaStreamNonBlocking);
    cudaEvent_t evX, evG[4], evF[4];
    cudaEventCreateWithFlags(&evX, cudaEventDisableTiming);
    for (int k = 0; k < 4; k++) {
        cudaEventCreateWithFlags(&evG[k], cudaEventDisableTiming);
        cudaEventCreateWithFlags(&evF[k], cudaEventDisableTiming);
    }

    // ---- prologue ----
    copy_pad_kernel<<<(NP * 32 + TB - 1) / TB, TB>>>(x, xb);                    // main 0
    cudaEventRecord(evX, 0);                          // xb ready (for s2's first gather)
    cvt_bf16_kernel<<<(SS * 384 * 32 + TB - 1) / TB, TB>>>(whh, whhb,
                                                           SS * 384 * 32);      // main 1
    zero2_ints<<<(NPS + TB - 1) / TB, TB, 0, s2>>>(ecntp, ecurp, NPS);          // s2
    // main launch idx 3 (PROFILED): gh GEMM for superstep (0,0)
    {
        GemmArgs ga;
        for (int s = 0; s < 3; s++) {
            ga.A[s] = xb;
            ga.B[s] = whhb + (size_t)s * 384 * 128;
            ga.bias[s] = bhh + s * 384;
            ga.C[s] = gh3 + (size_t)s * NP * 384;
        }
        bf16_gemm<<<g3, GEMM_T, BG_SMEM>>>(ga, 384, M_TILES);
    }
    // s2: CSR build + first gather (overlapped with gh GEMM + weight cvts)
    ecount_kernel<<<(EE + TB - 1) / TB, TB, 0, s2>>>(dst, eattr, ecntp, EE);
    scan_kernel<<<1, 1024, 0, s2>>>(ecntp, eoffp, NPS);
    fill_kernel<<<(EE + TB - 1) / TB, TB, 0, s2>>>(src, dst, eattr, eoffp, ecurp, bsrcp, EE);
    cudaStreamWaitEvent(s2, evX, 0);
    {
        Feat3 f; f.p[0] = xb; f.p[1] = xb; f.p[2] = xb;
        gather3_kernel<<<(SS * NP * 32 + TB - 1) / TB, TB, 0, s2>>>(eoffp, bsrcp, f, agg3);
    }
    cudaEventRecord(evG[0], s2);
    // main: remaining weight cvts + wc GEMM
    cvt_bf16_kernel<<<(SS * 384 * 32 + TB - 1) / TB, TB>>>(wih, wihb, SS * 384 * 32);
    cvt_bf16_kernel<<<(SS * 2 * 128 * 32 + TB - 1) / TB, TB>>>(W, Wb, SS * 2 * 128 * 32);
    {
        GemmArgs ga;
        for (int z = 0; z < 6; z++) {
            int s = z / 2, i = z % 2;
            ga.A[z] = wihb + (size_t)s * 384 * 128;
            ga.B[z] = Wb + (size_t)(s * 2 + i) * 128 * 128;
            ga.bias[z] = nullptr;
            ga.C[z] = wcb + (size_t)(s * 2 + i) * 384 * 128;
        }
        bf16_gemm<<<dim3(1, 3, 6), GEMM_T, BG_SMEM>>>(ga, 128, 3);
    }

    // ---- main loop: 4 supersteps; gather on s2 ∥ gh-GEMM on main ----
    int step = 0;
    for (int pass = 0; pass < 2; pass++) {
        for (int i = 0; i < 2; i++, step++) {
            if (step > 0) {
                // fork: gather depends on prior GRU output
                cudaEventRecord(evF[step], 0);
                cudaStreamWaitEvent(s2, evF[step], 0);
                Feat3 f;
                if (i == 0) { f.p[0] = xb; f.p[1] = xb; f.p[2] = xb; }
                else {
                    f.p[0] = hb3;
                    f.p[1] = hb3 + (size_t)NP * 128;
                    f.p[2] = hb3 + (size_t)2 * NP * 128;
                }
                gather3_kernel<<<(SS * NP * 32 + TB - 1) / TB, TB, 0, s2>>>(
                    eoffp, bsrcp, f, agg3);
                cudaEventRecord(evG[step], s2);
                // main: gh GEMM concurrent with gather
                GemmArgs ga;
                for (int s = 0; s < 3; s++) {
                    ga.A[s] = (i == 0) ? xb : (hb3 + (size_t)s * NP * 128);
                    ga.B[s] = whhb + (size_t)s * 384 * 128;
                    ga.bias[s] = bhh + s * 384;
                    ga.C[s] = gh3 + (size_t)s * NP * 384;
                }
                bf16_gemm<<<g3, GEMM_T, BG_SMEM>>>(ga, 384, M_TILES);
            }
            // join: gi GEMM needs gather output
            cudaStreamWaitEvent(0, evG[step], 0);
            {
                GemmArgs ga;
                for (int s = 0; s < 3; s++) {
                    ga.A[s] = agg3 + (size_t)s * NP * 128;
                    ga.B[s] = wcb + (size_t)(s * 2 + i) * 384 * 128;
                    ga.bias[s] = bih + s * 384;
                    ga.C[s] = gi3 + (size_t)s * NP * 384;
                }
                bf16_gemm<<<g3, GEMM_T, BG_SMEM>>>(ga, 384, M_TILES);
            }
            if (i == 0)
                gru3_first_kernel<<<dim3((NN * 32 + TB - 1) / TB, 3), TB>>>(
                    gi3, gh3, xb, hb3);
            else
                gru3_final_kernel<<<(NN * 32 + TB - 1) / TB, TB>>>(gi3, gh3, hb3, xb);
        }
    }

    // ---- pooling + MLP ----
    zero_kernel<<<(GG * DD / 4 + TB - 1) / TB, TB>>>(poolp, GG * DD / 4);
    zero_kernel<<<1, GG / 4>>>(cntp, GG / 4);
    cnt_kernel<<<(NN + TB - 1) / TB, TB>>>(batch, cntp, NN);
    pool_kernel<<<(NN * 32 + TB - 1) / TB, TB>>>(xb, batch, poolp);
    mlp_kernel<<<1, 256>>>(poolp, cntp, pt, fc1w, fc1b, fc2w, fc2b, fclw, fclb, out);

    // cleanup host objects when not capturing
    cudaStreamCaptureStatus cap = cudaStreamCaptureStatusNone;
    cudaStreamIsCapturing(0, &cap);
    if (cap == cudaStreamCaptureStatusNone) {
        cudaEventDestroy(evX);
        for (int k = 0; k < 4; k++) { cudaEventDestroy(evG[k]); cudaEventDestroy(evF[k]); }
        cudaStreamDestroy(s2);
    }
}

// round 14
// speedup vs baseline: 1.4001x; 1.0064x over previous
#include <cuda_runtime.h>
#include <cuda_bf16.h>
#include <math.h>
#include <stdint.h>

#define NN 100000
#define NP 100096
#define EE 600000
#define DD 128
#define SS 3
#define GG 64
#define OUTD 2
#define NPS (SS * NP)
#define M_TILES (NP / 128)        // 782

// ---------------- device scratch ----------------
__device__ __nv_bfloat16 g_xb[NP * DD];
__device__ __nv_bfloat16 g_hb3[SS * NP * DD];
__device__ __nv_bfloat16 g_agg3[SS * NP * DD];
__device__ __nv_bfloat16 g_gh3[SS * NP * 3 * DD];
__device__ __nv_bfloat16 g_wcb[SS * 3 * DD * DD];     // gate-interleaved combined (i merged below)
__device__ __nv_bfloat16 g_wcb2[SS * 3 * DD * DD];    // i=1 copy
__device__ __nv_bfloat16 g_wihb[SS * 3 * DD * DD];    // gate-interleaved rows
__device__ __nv_bfloat16 g_whhb[SS * 3 * DD * DD];
__device__ __nv_bfloat16 g_Wb[SS * 2 * DD * DD];
__device__ float g_bihr[SS * 3 * DD];                 // gate-interleaved bias
__device__ float g_pool[GG * DD];
__device__ float g_cnt[GG];
__device__ int   g_bsrc[EE];
__device__ int   g_ecnt[NPS];
__device__ int   g_ecur[NPS];
__device__ int   g_eoff[NPS + 1];

// ---------------- tiny utils ----------------
__global__ void zero_kernel(float* __restrict__ p, int n4) {
    int i = blockIdx.x * blockDim.x + threadIdx.x;
    if (i < n4) ((float4*)p)[i] = make_float4(0.f, 0.f, 0.f, 0.f);
}
__global__ void copy_pad_kernel(const float* __restrict__ x, __nv_bfloat16* __restrict__ xb) {
    int i = blockIdx.x * blockDim.x + threadIdx.x;
    if (i >= NP * 32) return;
    int n = i >> 5;
    float4 v = make_float4(0.f, 0.f, 0.f, 0.f);
    if (n < NN) v = ((const float4*)x)[i];
    *(__nv_bfloat162*)(xb + (size_t)i * 4)     = __floats2bfloat162_rn(v.x, v.y);
    *(__nv_bfloat162*)(xb + (size_t)i * 4 + 2) = __floats2bfloat162_rn(v.z, v.w);
}
__global__ void cvt_bf16_kernel(const float* __restrict__ src,
                                __nv_bfloat16* __restrict__ dst, int n4) {
    int i = blockIdx.x * blockDim.x + threadIdx.x;
    if (i >= n4) return;
    float4 v = ((const float4*)src)[i];
    *(__nv_bfloat162*)(dst + (size_t)i * 4)     = __floats2bfloat162_rn(v.x, v.y);
    *(__nv_bfloat162*)(dst + (size_t)i * 4 + 2) = __floats2bfloat162_rn(v.z, v.w);
}
// wih: rows reordered g*128+d -> d*3+g (per s), fp32 -> bf16
__global__ void cvt_wih_il_kernel(const float* __restrict__ wih,
                                  __nv_bfloat16* __restrict__ dst) {
    int i = blockIdx.x * blockDim.x + threadIdx.x;      // SS*384*32 float4 units
    if (i >= SS * 384 * 32) return;
    int s = i / (384 * 32);
    int rem = i - s * 384 * 32;
    int j = rem >> 5;
    int k4 = (rem & 31) * 4;
    int jil = (j & 127) * 3 + (j >> 7);
    float4 v = *(const float4*)(wih + (size_t)(s * 384 + j) * 128 + k4);
    __nv_bfloat16* o = dst + (size_t)(s * 384 + jil) * 128 + k4;
    *(__nv_bfloat162*)(o)     = __floats2bfloat162_rn(v.x, v.y);
    *(__nv_bfloat162*)(o + 2) = __floats2bfloat162_rn(v.z, v.w);
}
__global__ void bihr_kernel(const float* __restrict__ bih, float* __restrict__ bihr) {
    int i = blockIdx.x * blockDim.x + threadIdx.x;
    if (i >= SS * 384) return;
    int s = i / 384;
    int j = i - s * 384;
    int jil = (j & 127) * 3 + (j >> 7);
    bihr[s * 384 + jil] = bih[i];
}
__global__ void zero2_ints(int* __restrict__ a, int* __restrict__ b, int n) {
    int i = blockIdx.x * blockDim.x + threadIdx.x;
    if (i < n) { a[i] = 0; b[i] = 0; }
}

// ---------------- CSR build ----------------
__global__ void ecount_kernel(const int* __restrict__ dst, const int* __restrict__ attr,
                              int* __restrict__ cnt, int E) {
    int e = blockIdx.x * blockDim.x + threadIdx.x;
    if (e < E) atomicAdd(&cnt[attr[e] * NP + dst[e]], 1);
}
__global__ void scan_kernel(const int* __restrict__ cnt, int* __restrict__ off, int n) {
    __shared__ int ssum[1024];
    int t = threadIdx.x;
    int per = (n + 1023) / 1024;
    int b0 = t * per;
    int b1 = b0 + per; if (b1 > n) b1 = n; if (b0 > n) b0 = n;
    int s = 0;
    for (int i = b0; i < b1; i++) s += cnt[i];
    ssum[t] = s;
    __syncthreads();
    for (int d = 1; d < 1024; d <<= 1) {
        int v = (t >= d) ? ssum[t - d] : 0;
        __syncthreads();
        ssum[t] += v;
        __syncthreads();
    }
    int run = (t == 0) ? 0 : ssum[t - 1];
    if (t == 1023) off[n] = ssum[1023];
    for (int i = b0; i < b1; i++) { off[i] = run; run += cnt[i]; }
}
__global__ void fill_kernel(const int* __restrict__ src, const int* __restrict__ dst,
                            const int* __restrict__ attr, const int* __restrict__ off,
                            int* __restrict__ cur, int* __restrict__ bsrc, int E) {
    int e = blockIdx.x * blockDim.x + threadIdx.x;
    if (e >= E) return;
    int idx = attr[e] * NP + dst[e];
    int pos = off[idx] + atomicAdd(&cur[idx], 1);
    bsrc[pos] = src[e];
}

// ---------------- gather all 3 types ----------------
struct Feat3 { const __nv_bfloat16* p[3]; };

__global__ void gather3_kernel(const int* __restrict__ off, const int* __restrict__ bsrc,
                               Feat3 f, __nv_bfloat16* __restrict__ agg3) {
    int w = (blockIdx.x * blockDim.x + threadIdx.x) >> 5;
    int lane = threadIdx.x & 31;
    if (w >= SS * NP) return;
    int s = w / NP;
    const __nv_bfloat16* feat = f.p[s];
    int e0 = off[w], e1 = off[w + 1];
    float a0 = 0.f, a1 = 0.f, a2 = 0.f, a3 = 0.f;
    for (int e = e0; e < e1; e++) {
        int sn = bsrc[e];
        uint2 u = *(const uint2*)(feat + (size_t)sn * DD + lane * 4);
        __nv_bfloat162 p0 = *(__nv_bfloat162*)&u.x;
        __nv_bfloat162 p1 = *(__nv_bfloat162*)&u.y;
        float2 f0 = __bfloat1622float2(p0), f1 = __bfloat1622float2(p1);
        a0 += f0.x; a1 += f0.y; a2 += f1.x; a3 += f1.y;
    }
    if (e1 > e0) {
        float inv = 1.0f / (float)(e1 - e0);
        a0 *= inv; a1 *= inv; a2 *= inv; a3 *= inv;
    }
    uint2 o;
    *(__nv_bfloat162*)&o.x = __floats2bfloat162_rn(a0, a1);
    *(__nv_bfloat162*)&o.y = __floats2bfloat162_rn(a2, a3);
    *(uint2*)(agg3 + (size_t)w * DD + lane * 4) = o;
}

// ---------------- mma helpers ----------------
#define LDTB 136
__device__ __forceinline__ void cp16(void* s, const void* g) {
    uint32_t sa = (uint32_t)__cvta_generic_to_shared(s);
    asm volatile("cp.async.cg.shared.global [%0], [%1], 16;" :: "r"(sa), "l"(g));
}
__device__ __forceinline__ void ldm_x4(uint32_t* r, const __nv_bfloat16* p) {
    uint32_t sa = (uint32_t)__cvta_generic_to_shared(p);
    asm volatile("ldmatrix.sync.aligned.m8n8.x4.shared.b16 {%0,%1,%2,%3}, [%4];"
                 : "=r"(r[0]), "=r"(r[1]), "=r"(r[2]), "=r"(r[3]) : "r"(sa));
}
__device__ __forceinline__ void ldm_x2(uint32_t* r, const __nv_bfloat16* p) {
    uint32_t sa = (uint32_t)__cvta_generic_to_shared(p);
    asm volatile("ldmatrix.sync.aligned.m8n8.x2.shared.b16 {%0,%1}, [%2];"
                 : "=r"(r[0]), "=r"(r[1]) : "r"(sa));
}
__device__ __forceinline__ void mma16816(float* c, const uint32_t* a, const uint32_t* b) {
    asm volatile(
        "mma.sync.aligned.m16n8k16.row.col.f32.bf16.bf16.f32 "
        "{%0,%1,%2,%3}, {%4,%5,%6,%7}, {%8,%9}, {%0,%1,%2,%3};"
        : "+f"(c[0]), "+f"(c[1]), "+f"(c[2]), "+f"(c[3])
        : "r"(a[0]), "r"(a[1]), "r"(a[2]), "r"(a[3]), "r"(b[0]), "r"(b[1]));
}
__device__ __forceinline__ float tanhapx(float x) {
    float y;
    asm("tanh.approx.f32 %0, %1;" : "=f"(y) : "f"(x));
    return y;
}
__device__ __forceinline__ float sigf(float x) {
    return 0.5f * tanhapx(0.5f * x) + 0.5f;
}
__device__ __forceinline__ float4 ldbf4(const __nv_bfloat16* p) {
    uint2 u = *(const uint2*)p;
    __nv_bfloat162 a = *(__nv_bfloat162*)&u.x;
    __nv_bfloat162 b = *(__nv_bfloat162*)&u.y;
    float2 fa = __bfloat1622float2(a), fb = __bfloat1622float2(b);
    return make_float4(fa.x, fa.y, fb.x, fb.y);
}
__device__ __forceinline__ void stbf4(__nv_bfloat16* p, float4 v) {
    uint2 u;
    *(__nv_bfloat162*)&u.x = __floats2bfloat162_rn(v.x, v.y);
    *(__nv_bfloat162*)&u.y = __floats2bfloat162_rn(v.z, v.w);
    *(uint2*)p = u;
}

// ========== plain weights-stationary GEMM (gh + wc), R12 core ==========
#define SMB_B (128 * LDTB * 2)
#define SMB_A (128 * LDTB * 2)
#define BG_SMEM (SMB_B + 2 * SMB_A)  // 104448
#define GEMM_T 512

struct GemmArgs {
    const __nv_bfloat16* A[6];
    const __nv_bfloat16* B[6];
    const float* bias[6];
    __nv_bfloat16* C[6];
};

__global__ void __launch_bounds__(GEMM_T, 1)
bf16_gemm(GemmArgs ga, int J, int mtiles) {
    int z = blockIdx.z;
    const __nv_bfloat16* A = ga.A[z];
    const __nv_bfloat16* B = ga.B[z];
    const float* bias = ga.bias[z];
    __nv_bfloat16* C = ga.C[z];

    extern __shared__ char smx[];
    __nv_bfloat16* Bs = (__nv_bfloat16*)smx;
    __nv_bfloat16* Abuf0 = (__nv_bfloat16*)(smx + SMB_B);
    __nv_bfloat16* Abuf1 = (__nv_bfloat16*)(smx + SMB_B + SMB_A);

    int tid = threadIdx.x;
    int warp = tid >> 5;
    int lane = tid & 31;
    int mb = (warp >> 2) * 32;
    int nb = (warp & 3) * 32;
    int bn = blockIdx.x * 128;

    int mt = blockIdx.y;
    if (mt >= mtiles) return;

    for (int slot = tid; slot < 128 * 16; slot += GEMM_T) {
        int r = slot >> 4;
        int c8 = (slot & 15) * 8;
        cp16(Bs + r * LDTB + c8, B + (size_t)(bn + r) * 128 + c8);
    }
    asm volatile("cp.async.commit_group;");
    for (int slot = tid; slot < 128 * 16; slot += GEMM_T) {
        int r = slot >> 4;
        int c8 = (slot & 15) * 8;
        cp16(Abuf0 + r * LDTB + c8, A + (size_t)mt * 128 * 128 + (size_t)r * 128 + c8);
    }
    asm volatile("cp.async.commit_group;");
    asm volatile("cp.async.wait_group 1;");
    __syncthreads();

    uint32_t bf[4][8][2];
    {
        int lr = lane & 7;
        int ls = (lane >> 3) & 1;
#pragma unroll
        for (int nt = 0; nt < 4; nt++)
#pragma unroll
            for (int kt = 0; kt < 8; kt++)
                ldm_x2(bf[nt][kt], Bs + (nb + nt * 8 + lr) * LDTB + kt * 16 + ls * 8);
    }

    int buf = 0;
    while (mt < mtiles) {
        int nxt = mt + gridDim.y;
        bool pf = (nxt < mtiles);
        __nv_bfloat16* Acur = buf ? Abuf1 : Abuf0;
        __nv_bfloat16* Aalt = buf ? Abuf0 : Abuf1;
        if (pf) {
            for (int slot = tid; slot < 128 * 16; slot += GEMM_T) {
                int r = slot >> 4;
                int c8 = (slot & 15) * 8;
                cp16(Aalt + r * LDTB + c8,
                     A + (size_t)nxt * 128 * 128 + (size_t)r * 128 + c8);
            }
            asm volatile("cp.async.commit_group;");
            asm volatile("cp.async.wait_group 1;");
        } else {
            asm volatile("cp.async.wait_group 0;");
        }
        __syncthreads();

        float acc[2][4][4];
#pragma unroll
        for (int i = 0; i < 2; i++)
#pragma unroll
            for (int nt = 0; nt < 4; nt++)
#pragma unroll
                for (int e = 0; e < 4; e++) acc[i][nt][e] = 0.f;

        int q = lane >> 3;
        int arow = (q & 1) * 8 + (lane & 7);
        int acol = (q >> 1) * 8;
#pragma unroll
        for (int kt = 0; kt < 8; kt++) {
            uint32_t a[2][4];
#pragma unroll
            for (int i = 0; i < 2; i++)
                ldm_x4(a[i], Acur + (mb + i * 16 + arow) * LDTB + kt * 16 + acol);
#pragma unroll
            for (int i = 0; i < 2; i++)
#pragma unroll
                for (int nt = 0; nt < 4; nt++)
                    mma16816(acc[i][nt], a[i], bf[nt][kt]);
        }

        int bm = mt * 128;
#pragma unroll
        for (int i = 0; i < 2; i++) {
#pragma unroll
            for (int nt = 0; nt < 4; nt++) {
                int r0 = bm + mb + i * 16 + (lane >> 2);
                int cc = bn + nb + nt * 8 + ((lane & 3) << 1);
                float b0v = 0.f, b1v = 0.f;
                if (bias != nullptr) { b0v = bias[cc]; b1v = bias[cc + 1]; }
                *(__nv_bfloat162*)(C + (size_t)r0 * J + cc) =
                    __floats2bfloat162_rn(acc[i][nt][0] + b0v, acc[i][nt][1] + b1v);
                *(__nv_bfloat162*)(C + (size_t)(r0 + 8) * J + cc) =
                    __floats2bfloat162_rn(acc[i][nt][2] + b0v, acc[i][nt][3] + b1v);
            }
        }
        __syncthreads();
        mt = nxt;
        buf ^= 1;
    }
}

// ========== fused gi-GEMM + GRU epilogue (gate-interleaved Wc) ==========
// CTA tile 128(M) x 96(N=32 dims x 3 gates). Warp tile 32x24. 16 warps.
#define SMB_B2 (96 * LDTB * 2)           // 26112
#define FG_SMEM (SMB_B2 + 2 * SMB_A)     // 95744
#define STRC 104

struct FusedArgs {
    const __nv_bfloat16* A[3];      // agg3 per s
    const __nv_bfloat16* B[3];      // wcb interleaved per s
    const __nv_bfloat16* gh[3];     // gh3 per s
    const __nv_bfloat16* hold[3];   // xb or hb3[s]
    __nv_bfloat16* out[3];          // hb3[s]
    const float* bias[3];           // bihr per s
};

__global__ void __launch_bounds__(GEMM_T, 1)
gemm_gru(FusedArgs fa, int mtiles) {
    int s = blockIdx.z;
    const __nv_bfloat16* A = fa.A[s];
    const __nv_bfloat16* B = fa.B[s];
    const __nv_bfloat16* gh = fa.gh[s];
    const __nv_bfloat16* hold = fa.hold[s];
    __nv_bfloat16* outp = fa.out[s];
    const float* bias = fa.bias[s];

    extern __shared__ char smx[];
    __nv_bfloat16* Bs = (__nv_bfloat16*)smx;
    __nv_bfloat16* Abuf0 = (__nv_bfloat16*)(smx + SMB_B2);
    __nv_bfloat16* Abuf1 = (__nv_bfloat16*)(smx + SMB_B2 + SMB_A);

    int tid = threadIdx.x;
    int warp = tid >> 5;
    int lane = tid & 31;
    int mb = (warp >> 2) * 32;
    int nb = (warp & 3) * 24;
    int bnr = blockIdx.x * 96;     // interleaved col base
    int D0 = blockIdx.x * 32;      // dim base

    int mt = blockIdx.y;
    if (mt >= mtiles) return;

    // B stripe: 96 rows x 128
    for (int slot = tid; slot < 96 * 16; slot += GEMM_T) {
        int r = slot >> 4;
        int c8 = (slot & 15) * 8;
        cp16(Bs + r * LDTB + c8, B + (size_t)(bnr + r) * 128 + c8);
    }
    asm volatile("cp.async.commit_group;");
    for (int slot = tid; slot < 128 * 16; slot += GEMM_T) {
        int r = slot >> 4;
        int c8 = (slot & 15) * 8;
        cp16(Abuf0 + r * LDTB + c8, A + (size_t)mt * 128 * 128 + (size_t)r * 128 + c8);
    }
    asm volatile("cp.async.commit_group;");
    asm volatile("cp.async.wait_group 1;");
    __syncthreads();

    uint32_t bfr[3][8][2];
    {
        int lr = lane & 7;
        int ls = (lane >> 3) & 1;
#pragma unroll
        for (int nt = 0; nt < 3; nt++)
#pragma unroll
            for (int kt = 0; kt < 8; kt++)
                ldm_x2(bfr[nt][kt], Bs + (nb + nt * 8 + lr) * LDTB + kt * 16 + ls * 8);
    }

    int buf = 0;
    while (mt < mtiles) {
        int nxt = mt + gridDim.y;
        bool pf = (nxt < mtiles);
        __nv_bfloat16* Acur = buf ? Abuf1 : Abuf0;
        __nv_bfloat16* Aalt = buf ? Abuf0 : Abuf1;
        if (pf) {
            for (int slot = tid; slot < 128 * 16; slot += GEMM_T) {
                int r = slot >> 4;
                int c8 = (slot & 15) * 8;
                cp16(Aalt + r * LDTB + c8,
                     A + (size_t)nxt * 128 * 128 + (size_t)r * 128 + c8);
            }
            asm volatile("cp.async.commit_group;");
            asm volatile("cp.async.wait_group 1;");
        } else {
            asm volatile("cp.async.wait_group 0;");
        }
        __syncthreads();

        float acc[2][3][4];
#pragma unroll
        for (int i = 0; i < 2; i++)
#pragma unroll
            for (int nt = 0; nt < 3; nt++)
#pragma unroll
                for (int e = 0; e < 4; e++) acc[i][nt][e] = 0.f;

        int q = lane >> 3;
        int arow = (q & 1) * 8 + (lane & 7);
        int acol = (q >> 1) * 8;
#pragma unroll
        for (int kt = 0; kt < 8; kt++) {
            uint32_t a[2][4];
#pragma unroll
            for (int i = 0; i < 2; i++)
                ldm_x4(a[i], Acur + (mb + i * 16 + arow) * LDTB + kt * 16 + acol);
#pragma unroll
            for (int i = 0; i < 2; i++)
#pragma unroll
                for (int nt = 0; nt < 3; nt++)
                    mma16816(acc[i][nt], a[i], bfr[nt][kt]);
        }
        __syncthreads();   // all Acur reads done before staging into it

        // stage gi (+bias) as bf16 into Acur region: Cs[128][STRC]
        __nv_bfloat16* Cs = Acur;
#pragma unroll
        for (int i = 0; i < 2; i++) {
#pragma unroll
            for (int nt = 0; nt < 3; nt++) {
                int r0 = mb + i * 16 + (lane >> 2);
                int cc = nb + nt * 8 + ((lane & 3) << 1);
                float b0v = bias[bnr + cc];
                float b1v = bias[bnr + cc + 1];
                *(__nv_bfloat162*)(Cs + r0 * STRC + cc) =
                    __floats2bfloat162_rn(acc[i][nt][0] + b0v, acc[i][nt][1] + b1v);
                *(__nv_bfloat162*)(Cs + (r0 + 8) * STRC + cc) =
                    __floats2bfloat162_rn(acc[i][nt][2] + b0v, acc[i][nt][3] + b1v);
            }
        }
        __syncthreads();

        // GRU epilogue: 128 rows x 32 dims; thread handles 2 groups of 4 dims
        int bm = mt * 128;
#pragma unroll
        for (int it = 0; it < 2; it++) {
            int g = tid + it * GEMM_T;          // 0..1023
            int row = g >> 3;
            int d4 = (g & 7) << 2;
            int grow = bm + row;
            float4 ir, iz, in4;
#pragma unroll
            for (int l = 0; l < 4; l++) {
                const __nv_bfloat16* cp = Cs + row * STRC + (d4 + l) * 3;
                ((float*)&ir)[l]  = __bfloat162float(cp[0]);
                ((float*)&iz)[l]  = __bfloat162float(cp[1]);
                ((float*)&in4)[l] = __bfloat162float(cp[2]);
            }
            const __nv_bfloat16* ghr = gh + (size_t)grow * 384 + D0 + d4;
            float4 hr = ldbf4(ghr);
            float4 hz = ldbf4(ghr + 128);
            float4 hn = ldbf4(ghr + 256);
            float4 h = ldbf4(hold + (size_t)grow * 128 + D0 + d4);
            float4 o;
            { float r = sigf(ir.x + hr.x), z = sigf(iz.x + hz.x);
              float nn = tanhapx(in4.x + r * hn.x); o.x = (1.f - z) * nn + z * h.x; }
            { float r = sigf(ir.y + hr.y), z = sigf(iz.y + hz.y);
              float nn = tanhapx(in4.y + r * hn.y); o.y = (1.f - z) * nn + z * h.y; }
            { float r = sigf(ir.z + hr.z), z = sigf(iz.z + hz.z);
              float nn = tanhapx(in4.z + r * hn.z); o.z = (1.f - z) * nn + z * h.z; }
            { float r = sigf(ir.w + hr.w), z = sigf(iz.w + hz.w);
              float nn = tanhapx(in4.w + r * hn.w); o.w = (1.f - z) * nn + z * h.w; }
            stbf4(outp + (size_t)grow * 128 + D0 + d4, o);
        }
        __syncthreads();
        mt = nxt;
        buf ^= 1;
    }
}

// xb = mean over s of hb3[s]
__global__ void avg3_kernel(const __nv_bfloat16* __restrict__ hb3,
                            __nv_bfloat16* __restrict__ xb) {
    int i = blockIdx.x * blockDim.x + threadIdx.x;
    if (i >= NP * 32) return;
    size_t p = (size_t)i * 4;
    float4 a = ldbf4(hb3 + p);
    float4 b = ldbf4(hb3 + (size_t)NP * 128 + p);
    float4 c = ldbf4(hb3 + (size_t)2 * NP * 128 + p);
    float4 v;
    v.x = (a.x + b.x + c.x) * (1.0f / 3.0f);
    v.y = (a.y + b.y + c.y) * (1.0f / 3.0f);
    v.z = (a.z + b.z + c.z) * (1.0f / 3.0f);
    v.w = (a.w + b.w + c.w) * (1.0f / 3.0f);
    stbf4(xb + p, v);
}

// ---------------- pooling / MLP ----------------
__global__ void cnt_kernel(const int* __restrict__ batch, float* __restrict__ cnt, int n) {
    int i = blockIdx.x * blockDim.x + threadIdx.x;
    if (i < n) atomicAdd(&cnt[batch[i]], 1.0f);
}
__global__ void pool_kernel(const __nv_bfloat16* __restrict__ xb, const int* __restrict__ batch,
                            float* __restrict__ pool) {
    int idx = blockIdx.x * blockDim.x + threadIdx.x;
    if (idx >= NN * 32) return;
    int n = idx >> 5;
    int c = (idx & 31) * 4;
    int g = batch[n];
    float4 v = ldbf4(xb + (size_t)n * 128 + c);
    float* o = pool + (size_t)g * 128 + c;
    asm volatile("red.global.add.v4.f32 [%0], {%1,%2,%3,%4};"
                 :: "l"(o), "f"(v.x), "f"(v.y), "f"(v.z), "f"(v.w) : "memory");
}
__global__ void mlp_kernel(const float* __restrict__ pool, const float* __restrict__ cnt,
                           const float* __restrict__ pt,
                           const float* __restrict__ fc1w, const float* __restrict__ fc1b,
                           const float* __restrict__ fc2w, const float* __restrict__ fc2b,
                           const float* __restrict__ fclw, const float* __restrict__ fclb,
                           float* __restrict__ out) {
    __shared__ float h1[GG * 80];
    __shared__ float h2[GG * 80];
    int tid = threadIdx.x;
    for (int t = tid; t < GG * 80; t += blockDim.x) {
        int g = t / 80, j = t - (t / 80) * 80;
        float ic = 1.0f / fmaxf(cnt[g], 1.0f);
        float acc = fc1b[j];
        const float* w = fc1w + j * 129;
        const float* p = pool + g * 128;
        for (int k = 0; k < 128; k++) acc = fmaf(p[k] * ic, w[k], acc);
        acc = fmaf(pt[g], w[128], acc);
        h1[t] = acc > 0.f ? acc : 0.01f * acc;
    }
    __syncthreads();
    for (int t = tid; t < GG * 80; t += blockDim.x) {
        int g = t / 80, j = t - (t / 80) * 80;
        float acc = fc2b[j];
        const float* w = fc2w + j * 80;
        const float* hh = h1 + g * 80;
        for (int k = 0; k < 80; k++) acc = fmaf(hh[k], w[k], acc);
        h2[t] = acc > 0.f ? acc : 0.01f * acc;
    }
    __syncthreads();
    for (int t = tid; t < GG * OUTD; t += blockDim.x) {
        int g = t / OUTD, o = t - (t / OUTD) * OUTD;
        float acc = fclb[o];
        const float* w = fclw + o * 80;
        const float* hh = h2 + g * 80;
        for (int k = 0; k < 80; k++) acc = fmaf(hh[k], w[k], acc);
        out[t] = acc;
    }
}

// ---------------- host launcher ----------------
extern "C" void kernel_launch(void* const* d_in, const int* in_sizes, int n_in,
                              void* d_out, int out_size) {
    (void)in_sizes; (void)n_in; (void)out_size;
    const float* x     = (const float*)d_in[0];
    const int*   eidx  = (const int*)d_in[1];
    const int*   eattr = (const int*)d_in[2];
    const int*   batch = (const int*)d_in[3];
    const float* pt    = (const float*)d_in[4];
    const float* W     = (const float*)d_in[5];
    const float* wih   = (const float*)d_in[6];
    const float* whh   = (const float*)d_in[7];
    const float* bih   = (const float*)d_in[8];
    const float* bhh   = (const float*)d_in[9];
    const float* fc1w  = (const float*)d_in[10];
    const float* fc1b  = (const float*)d_in[11];
    const float* fc2w  = (const float*)d_in[12];
    const float* fc2b  = (const float*)d_in[13];
    const float* fclw  = (const float*)d_in[14];
    const float* fclb  = (const float*)d_in[15];
    float* out = (float*)d_out;

    const int* src = eidx;
    const int* dst = eidx + EE;

    float *poolp, *cntp, *bihrp;
    __nv_bfloat16 *xb, *hb3, *agg3, *gh3, *wcb, *wcb2, *wihb, *whhb, *Wb;
    int *bsrcp, *ecntp, *ecurp, *eoffp;
    cudaGetSymbolAddress((void**)&xb,    g_xb);
    cudaGetSymbolAddress((void**)&hb3,   g_hb3);
    cudaGetSymbolAddress((void**)&agg3,  g_agg3);
    cudaGetSymbolAddress((void**)&gh3,   g_gh3);
    cudaGetSymbolAddress((void**)&wcb,   g_wcb);
    cudaGetSymbolAddress((void**)&wcb2,  g_wcb2);
    cudaGetSymbolAddress((void**)&wihb,  g_wihb);
    cudaGetSymbolAddress((void**)&whhb,  g_whhb);
    cudaGetSymbolAddress((void**)&Wb,    g_Wb);
    cudaGetSymbolAddress((void**)&bihrp, g_bihr);
    cudaGetSymbolAddress((void**)&poolp, g_pool);
    cudaGetSymbolAddress((void**)&cntp,  g_cnt);
    cudaGetSymbolAddress((void**)&bsrcp, g_bsrc);
    cudaGetSymbolAddress((void**)&ecntp, g_ecnt);
    cudaGetSymbolAddress((void**)&ecurp, g_ecur);
    cudaGetSymbolAddress((void**)&eoffp, g_eoff);

    cudaFuncSetAttribute(bf16_gemm, cudaFuncAttributeMaxDynamicSharedMemorySize, BG_SMEM);
    cudaFuncSetAttribute(gemm_gru, cudaFuncAttributeMaxDynamicSharedMemorySize, FG_SMEM);

    const int TB = 256;
    dim3 g3(3, 16, 3);       // gh GEMM
    dim3 fg(4, 12, 3);       // fused gi+GRU (144 CTAs)

    cudaStream_t s2;
    cudaStreamCreateWithFlags(&s2, cudaStreamNonBlocking);
    cudaEvent_t evX, evG[4], evF[4];
    cudaEventCreateWithFlags(&evX, cudaEventDisableTiming);
    for (int k = 0; k < 4; k++) {
        cudaEventCreateWithFlags(&evG[k], cudaEventDisableTiming);
        cudaEventCreateWithFlags(&evF[k], cudaEventDisableTiming);
    }

    // ---- prologue ----
    copy_pad_kernel<<<(NP * 32 + TB - 1) / TB, TB>>>(x, xb);                    // main 0
    cudaEventRecord(evX, 0);
    cvt_bf16_kernel<<<(SS * 384 * 32 + TB - 1) / TB, TB>>>(whh, whhb,
                                                           SS * 384 * 32);      // main 1
    zero2_ints<<<(NPS + TB - 1) / TB, TB, 0, s2>>>(ecntp, ecurp, NPS);          // s2
    // main idx 3 (PROFILED): gh GEMM for superstep (0,0)
    {
        GemmArgs ga;
        for (int s = 0; s < 3; s++) {
            ga.A[s] = xb;
            ga.B[s] = whhb + (size_t)s * 384 * 128;
            ga.bias[s] = bhh + s * 384;
            ga.C[s] = gh3 + (size_t)s * NP * 384;
        }
        bf16_gemm<<<g3, GEMM_T, BG_SMEM>>>(ga, 384, M_TILES);
    }
    // s2: CSR + first gather
    ecount_kernel<<<(EE + TB - 1) / TB, TB, 0, s2>>>(dst, eattr, ecntp, EE);
    scan_kernel<<<1, 1024, 0, s2>>>(ecntp, eoffp, NPS);
    fill_kernel<<<(EE + TB - 1) / TB, TB, 0, s2>>>(src, dst, eattr, eoffp, ecurp, bsrcp, EE);
    cudaStreamWaitEvent(s2, evX, 0);
    {
        Feat3 f; f.p[0] = xb; f.p[1] = xb; f.p[2] = xb;
        gather3_kernel<<<(SS * NP * 32 + TB - 1) / TB, TB, 0, s2>>>(eoffp, bsrcp, f, agg3);
    }
    cudaEventRecord(evG[0], s2);
    // main: weight prep (interleaved)
    cvt_wih_il_kernel<<<(SS * 384 * 32 + TB - 1) / TB, TB>>>(wih, wihb);
    cvt_bf16_kernel<<<(SS * 2 * 128 * 32 + TB - 1) / TB, TB>>>(W, Wb, SS * 2 * 128 * 32);
    bihr_kernel<<<(SS * 384 + TB - 1) / TB, TB>>>(bih, bihrp);
    // wc GEMMs (rows already interleaved via A): z in 0..5 -> (s, i)
    {
        GemmArgs ga;
        for (int z = 0; z < 6; z++) {
            int s = z / 2, i = z % 2;
            ga.A[z] = wihb + (size_t)s * 384 * 128;
            ga.B[z] = Wb + (size_t)(s * 2 + i) * 128 * 128;
            ga.bias[z] = nullptr;
            ga.C[z] = (i == 0 ? wcb : wcb2) + (size_t)s * 384 * 128;
        }
        bf16_gemm<<<dim3(1, 3, 6), GEMM_T, BG_SMEM>>>(ga, 128, 3);
    }

    // ---- main loop: 4 supersteps ----
    int step = 0;
    for (int pass = 0; pass < 2; pass++) {
        for (int i = 0; i < 2; i++, step++) {
            if (step > 0) {
                cudaEventRecord(evF[step], 0);
                cudaStreamWaitEvent(s2, evF[step], 0);
                Feat3 f;
                if (i == 0) { f.p[0] = xb; f.p[1] = xb; f.p[2] = xb; }
                else {
                    f.p[0] = hb3;
                    f.p[1] = hb3 + (size_t)NP * 128;
                    f.p[2] = hb3 + (size_t)2 * NP * 128;
                }
                gather3_kernel<<<(SS * NP * 32 + TB - 1) / TB, TB, 0, s2>>>(
                    eoffp, bsrcp, f, agg3);
                cudaEventRecord(evG[step], s2);
                GemmArgs ga;
                for (int s = 0; s < 3; s++) {
                    ga.A[s] = (i == 0) ? xb : (hb3 + (size_t)s * NP * 128);
                    ga.B[s] = whhb + (size_t)s * 384 * 128;
                    ga.bias[s] = bhh + s * 384;
                    ga.C[s] = gh3 + (size_t)s * NP * 384;
                }
                bf16_gemm<<<g3, GEMM_T, BG_SMEM>>>(ga, 384, M_TILES);
            }
            cudaStreamWaitEvent(0, evG[step], 0);
            {
                FusedArgs fa;
                for (int s = 0; s < 3; s++) {
                    fa.A[s] = agg3 + (size_t)s * NP * 128;
                    fa.B[s] = (i == 0 ? wcb : wcb2) + (size_t)s * 384 * 128;
                    fa.gh[s] = gh3 + (size_t)s * NP * 384;
                    fa.hold[s] = (i == 0) ? xb : (hb3 + (size_t)s * NP * 128);
                    fa.out[s] = hb3 + (size_t)s * NP * 128;
                    fa.bias[s] = bihrp + s * 384;
                }
                gemm_gru<<<fg, GEMM_T, FG_SMEM>>>(fa, M_TILES);
            }
            if (i == 1)
                avg3_kernel<<<(NP * 32 + TB - 1) / TB, TB>>>(hb3, xb);
        }
    }

    // ---- pooling + MLP ----
    zero_kernel<<<(GG * DD / 4 + TB - 1) / TB, TB>>>(poolp, GG * DD / 4);
    zero_kernel<<<1, GG / 4>>>(cntp, GG / 4);
    cnt_kernel<<<(NN + TB - 1) / TB, TB>>>(batch, cntp, NN);
    pool_kernel<<<(NN * 32 + TB - 1) / TB, TB>>>(xb, batch, poolp);
    mlp_kernel<<<1, 256>>>(poolp, cntp, pt, fc1w, fc1b, fc2w, fc2b, fclw, fclb, out);

    cudaStreamCaptureStatus cap = cudaStreamCaptureStatusNone;
    cudaStreamIsCapturing(0, &cap);
    if (cap == cudaStreamCaptureStatusNone) {
        cudaEventDestroy(evX);
        for (int k = 0; k < 4; k++) { cudaEventDestroy(evG[k]); cudaEventDestroy(evF[k]); }
        cudaStreamDestroy(s2);
    }
}